// round 1
// baseline (speedup 1.0000x reference)
#include <cuda_runtime.h>
#include <math.h>

#define NATOMS 50000
#define NEDGES 800000
#define ELEM   64
#define DOUT   128
#define BN_EPS 1e-5f

// ---------------- scratch (device globals; no allocation allowed) ----------------
__device__ float g_P1[(size_t)NATOMS * DOUT];   // atom @ W1 + b   (25.6 MB)
__device__ float g_P2[(size_t)NATOMS * DOUT];   // atom @ W2       (25.6 MB)
__device__ float g_Y [(size_t)NEDGES * DOUT];   // pre-BN edge features (409.6 MB)
__device__ int   g_rowptr[NATOMS + 1];
__device__ float g_colsum[DOUT];
__device__ float g_colsq [DOUT];
__device__ float g_a1[DOUT], g_c1[DOUT];
__device__ float g_sumed[(size_t)NATOMS * ELEM];
__device__ float g_s2[ELEM], g_q2[ELEM];
__device__ float g_a2[ELEM], g_c2[ELEM];

// ---------------- helpers ----------------
__device__ __forceinline__ float softplusf(float x) {
    // jax.nn.softplus: log1p(exp(-|x|)) + max(x, 0)   (numerically stable)
    return log1pf(expf(-fabsf(x))) + fmaxf(x, 0.0f);
}
__device__ __forceinline__ float sigmoidf(float x) {
    return 1.0f / (1.0f + expf(-x));
}
__device__ __forceinline__ void fma4(float4& a, float x, const float4 w) {
    a.x += x * w.x; a.y += x * w.y; a.z += x * w.z; a.w += x * w.w;
}
__device__ __forceinline__ float4 add4(float4 a, float4 b) {
    return make_float4(a.x + b.x, a.y + b.y, a.z + b.z, a.w + b.w);
}

// ---------------- kernels ----------------

// zero the tiny stat accumulators (re-zeroed on every graph replay)
__global__ void k_init() {
    int t = threadIdx.x;
    if (t < DOUT) { g_colsum[t] = 0.f; g_colsq[t] = 0.f; }
    if (t < ELEM) { g_s2[t] = 0.f; g_q2[t] = 0.f; }
}

// CSR row pointers from the SORTED self_fea_idx (binary search per atom)
__global__ void k_rowptr(const int* __restrict__ sidx) {
    int a = blockIdx.x * blockDim.x + threadIdx.x;
    if (a > NATOMS) return;
    int lo = 0, hi = NEDGES;
    while (lo < hi) {
        int mid = (lo + hi) >> 1;
        if (sidx[mid] < a) lo = mid + 1; else hi = mid;
    }
    g_rowptr[a] = lo;
}

// P1 = atom @ W[0:64]   + b ;  P2 = atom @ W[64:128]
__global__ void __launch_bounds__(256) k_precompute(const float* __restrict__ atom,
                                                    const float* __restrict__ W,
                                                    const float* __restrict__ bias) {
    __shared__ float sW[64][DOUT];   // 32 KB
    __shared__ float sAt[32][ELEM];  //  8 KB
    const int tid = threadIdx.x;
    const int ab = blockIdx.x * 32;
    const int nvalid = min(32, NATOMS - ab);

    #pragma unroll
    for (int p = 0; p < 2; p++) {                 // 32*64 floats = 512 float4
        int i4 = tid + p * 256;
        int a = i4 >> 4, kv = i4 & 15;
        float4 v = make_float4(0.f, 0.f, 0.f, 0.f);
        if (a < nvalid) v = *(const float4*)(atom + (size_t)(ab + a) * ELEM + kv * 4);
        *(float4*)&sAt[a][kv * 4] = v;
    }

    const int a  = tid >> 3;          // 32 atoms, 8 thread-groups each
    const int ob = (tid & 7) * 16;    // 16 output cols per thread

    for (int phase = 0; phase < 2; phase++) {
        __syncthreads();              // protects sW reuse + sAt initial load
        #pragma unroll
        for (int p = 0; p < 8; p++) { // 64*128 floats = 2048 float4
            int i4 = tid + p * 256;
            int k = i4 >> 5, j4 = i4 & 31;
            *(float4*)&sW[k][j4 * 4] =
                *(const float4*)(W + (size_t)(phase * 64 + k) * DOUT + j4 * 4);
        }
        __syncthreads();

        float4 acc[4];
        #pragma unroll
        for (int q = 0; q < 4; q++) acc[q] = make_float4(0.f, 0.f, 0.f, 0.f);
        #pragma unroll 8
        for (int k = 0; k < 64; k++) {
            float x = sAt[a][k];
            #pragma unroll
            for (int q = 0; q < 4; q++) fma4(acc[q], x, *(float4*)&sW[k][ob + q * 4]);
        }
        if (a < nvalid) {
            float* dst = (phase == 0 ? g_P1 : g_P2) + (size_t)(ab + a) * DOUT + ob;
            #pragma unroll
            for (int q = 0; q < 4; q++) {
                float4 v = acc[q];
                if (phase == 0) v = add4(v, *(const float4*)(bias + ob + q * 4));
                *(float4*)(dst + q * 4) = v;
            }
        }
    }
}

// Pass 1: y = nbr_fea @ W3 + P1[self] + P2[nbr]  (128x128x64 SGEMM tile),
// materialize Y, accumulate per-column sum / sumsq for BN1.
__global__ void __launch_bounds__(256, 2) k_y(const float* __restrict__ nbr,
                                              const int* __restrict__ sidx,
                                              const int* __restrict__ nidx,
                                              const float* __restrict__ W) {
    extern __shared__ float sh[];
    float (*sA)[68]   = (float (*)[68])sh;               // [128][68]  nbr tile (padded)
    float (*sB)[DOUT] = (float (*)[DOUT])(sh + 128 * 68); // [64][128]  W3

    const int tid = threadIdx.x;
    const int eb  = blockIdx.x * 128;

    #pragma unroll
    for (int p = 0; p < 8; p++) {                 // 128*64 floats = 2048 float4
        int i4 = tid + p * 256;
        int e = i4 >> 4, kv = i4 & 15;
        float4 v = *(const float4*)(nbr + (size_t)(eb + e) * ELEM + kv * 4);
        *(float4*)&sA[e][kv * 4] = v;
    }
    #pragma unroll
    for (int p = 0; p < 8; p++) {                 // W3 = W rows 128..191
        int i4 = tid + p * 256;
        int k = i4 >> 5, j4 = i4 & 31;
        *(float4*)&sB[k][j4 * 4] = *(const float4*)(W + (size_t)(128 + k) * DOUT + j4 * 4);
    }
    __syncthreads();

    const int ty = tid >> 4, tx = tid & 15;
    const int r0 = ty * 8, c0 = tx * 8;

    float4 accA[8], accB[8];
    #pragma unroll
    for (int i = 0; i < 8; i++) {
        accA[i] = make_float4(0.f, 0.f, 0.f, 0.f);
        accB[i] = make_float4(0.f, 0.f, 0.f, 0.f);
    }

    #pragma unroll 8
    for (int k = 0; k < 64; k++) {
        float4 b0 = *(float4*)&sB[k][c0];
        float4 b1 = *(float4*)&sB[k][c0 + 4];
        #pragma unroll
        for (int i = 0; i < 8; i++) {
            float x = sA[r0 + i][k];
            fma4(accA[i], x, b0);
            fma4(accB[i], x, b1);
        }
    }

    float cs[8] = {0.f}, cq[8] = {0.f};
    #pragma unroll
    for (int i = 0; i < 8; i++) {
        int e = eb + r0 + i;
        int s = sidx[e];
        int n = nidx[e];
        const float* p1 = g_P1 + (size_t)s * DOUT + c0;
        const float* p2 = g_P2 + (size_t)n * DOUT + c0;
        float4 y0 = add4(add4(accA[i], *(const float4*)p1),       *(const float4*)p2);
        float4 y1 = add4(add4(accB[i], *(const float4*)(p1 + 4)), *(const float4*)(p2 + 4));
        float* dst = g_Y + (size_t)e * DOUT + c0;
        *(float4*)dst       = y0;
        *(float4*)(dst + 4) = y1;
        cs[0] += y0.x; cq[0] += y0.x * y0.x;  cs[1] += y0.y; cq[1] += y0.y * y0.y;
        cs[2] += y0.z; cq[2] += y0.z * y0.z;  cs[3] += y0.w; cq[3] += y0.w * y0.w;
        cs[4] += y1.x; cq[4] += y1.x * y1.x;  cs[5] += y1.y; cq[5] += y1.y * y1.y;
        cs[6] += y1.z; cq[6] += y1.z * y1.z;  cs[7] += y1.w; cq[7] += y1.w * y1.w;
    }

    __syncthreads();                       // sA no longer needed: reuse as stat buffer
    float* shS = sh;
    float* shQ = sh + DOUT;
    if (tid < DOUT) { shS[tid] = 0.f; shQ[tid] = 0.f; }
    __syncthreads();
    #pragma unroll
    for (int j = 0; j < 8; j++) {
        atomicAdd(&shS[c0 + j], cs[j]);
        atomicAdd(&shQ[c0 + j], cq[j]);
    }
    __syncthreads();
    if (tid < DOUT) {
        atomicAdd(&g_colsum[tid], shS[tid]);
        atomicAdd(&g_colsq[tid],  shQ[tid]);
    }
}

__global__ void k_bn1fin(const float* __restrict__ gamma, const float* __restrict__ beta) {
    int j = threadIdx.x;   // 128 threads
    float mean = g_colsum[j] * (1.0f / NEDGES);
    float var  = g_colsq[j] * (1.0f / NEDGES) - mean * mean;
    float aa = gamma[j] * rsqrtf(var + BN_EPS);
    g_a1[j] = aa;
    g_c1[j] = beta[j] - mean * aa;
}

// Pass 2: BN1 + sigmoid*softplus + deterministic segment sum (CSR, no atomics).
// blockDim = (64, 4): thread = (column j, atom lane)
__global__ void __launch_bounds__(256) k_msg() {
    const int j = threadIdx.x;
    const int a = blockIdx.x * 4 + threadIdx.y;
    if (a >= NATOMS) return;
    const float a1f = g_a1[j],      c1f = g_c1[j];
    const float a1c = g_a1[j + 64], c1c = g_c1[j + 64];
    const int e0 = g_rowptr[a];
    const int e1 = g_rowptr[a + 1];
    float sum = 0.f;
    for (int e = e0; e < e1; e++) {
        const float* row = g_Y + (size_t)e * DOUT;
        float yf = row[j]      * a1f + c1f;   // filter half
        float yc = row[j + 64] * a1c + c1c;   // core half
        sum += sigmoidf(yf) * softplusf(yc);
    }
    g_sumed[(size_t)a * ELEM + j] = sum;
}

__global__ void k_bn2stats() {
    const int tid = blockIdx.x * blockDim.x + threadIdx.x;
    const int col = threadIdx.x & 63;          // stride is a multiple of 64
    const int stride = gridDim.x * blockDim.x;
    float s = 0.f, q = 0.f;
    for (int i = tid; i < NATOMS * ELEM; i += stride) {
        float v = g_sumed[i];
        s += v; q += v * v;
    }
    __shared__ float shS[ELEM], shQ[ELEM];
    if (threadIdx.x < ELEM) { shS[threadIdx.x] = 0.f; shQ[threadIdx.x] = 0.f; }
    __syncthreads();
    atomicAdd(&shS[col], s);
    atomicAdd(&shQ[col], q);
    __syncthreads();
    if (threadIdx.x < ELEM) {
        atomicAdd(&g_s2[threadIdx.x], shS[threadIdx.x]);
        atomicAdd(&g_q2[threadIdx.x], shQ[threadIdx.x]);
    }
}

__global__ void k_bn2fin(const float* __restrict__ gamma, const float* __restrict__ beta) {
    int j = threadIdx.x;   // 64 threads
    float mean = g_s2[j] * (1.0f / NATOMS);
    float var  = g_q2[j] * (1.0f / NATOMS) - mean * mean;
    float aa = gamma[j] * rsqrtf(var + BN_EPS);
    g_a2[j] = aa;
    g_c2[j] = beta[j] - mean * aa;
}

__global__ void k_final(const float* __restrict__ atom, float* __restrict__ out) {
    int i = blockIdx.x * blockDim.x + threadIdx.x;
    if (i >= NATOMS * ELEM) return;
    int j = i & 63;
    float v = atom[i] + g_sumed[i] * g_a2[j] + g_c2[j];
    out[i] = softplusf(v);
}

// ---------------- launch ----------------
extern "C" void kernel_launch(void* const* d_in, const int* in_sizes, int n_in,
                              void* d_out, int out_size) {
    const float* atom = (const float*)d_in[0];
    const float* nbr  = (const float*)d_in[1];
    const int*   sidx = (const int*)d_in[2];
    const int*   nidx = (const int*)d_in[3];
    const float* W    = (const float*)d_in[4];
    const float* bias = (const float*)d_in[5];
    const float* g1   = (const float*)d_in[6];
    const float* be1  = (const float*)d_in[7];
    const float* g2   = (const float*)d_in[8];
    const float* be2  = (const float*)d_in[9];
    float* out = (float*)d_out;

    const int SMEM_Y = (128 * 68 + 64 * DOUT) * (int)sizeof(float);  // 67584 B
    cudaFuncSetAttribute(k_y, cudaFuncAttributeMaxDynamicSharedMemorySize, SMEM_Y);

    k_init<<<1, 128>>>();
    k_precompute<<<(NATOMS + 31) / 32, 256>>>(atom, W, bias);
    k_rowptr<<<(NATOMS + 1 + 255) / 256, 256>>>(sidx);
    k_y<<<NEDGES / 128, 256, SMEM_Y>>>(nbr, sidx, nidx, W);
    k_bn1fin<<<1, DOUT>>>(g1, be1);
    dim3 mblk(64, 4);
    k_msg<<<(NATOMS + 3) / 4, mblk>>>();
    k_bn2stats<<<128, 256>>>();
    k_bn2fin<<<1, ELEM>>>(g2, be2);
    k_final<<<(NATOMS * ELEM + 255) / 256, 256>>>(atom, out);
}

// round 3
// speedup vs baseline: 1.4306x; 1.4306x over previous
#include <cuda_runtime.h>
#include <cuda_bf16.h>
#include <cuda_fp16.h>
#include <mma.h>
#include <math.h>
#include <stdint.h>

using namespace nvcuda;

#define NATOMS 50000
#define NEDGES 800000
#define ELEM   64
#define DOUT   128
#define BN_EPS 1e-5f
#define NTILES (NEDGES / 128)     // 6250
#define GRID_Y 148                // persistent, 1 CTA/SM

// ---------------- scratch (device globals; no allocation allowed) ----------------
__device__ float  g_P1[(size_t)NATOMS * DOUT];   // atom @ W1 + b   (25.6 MB)
__device__ float  g_P2[(size_t)NATOMS * DOUT];   // atom @ W2       (25.6 MB)
__device__ __half g_Yh[(size_t)NEDGES * DOUT];   // pre-BN edge features, fp16 (204.8 MB)
__device__ int    g_rowptr[NATOMS + 1];
__device__ float  g_colsum[DOUT];
__device__ float  g_colsq [DOUT];
__device__ float  g_a1[DOUT], g_c1[DOUT];
__device__ float  g_sumed[(size_t)NATOMS * ELEM];
__device__ float  g_s2[ELEM], g_q2[ELEM];
__device__ float  g_a2[ELEM], g_c2[ELEM];

// ---------------- helpers ----------------
__device__ __forceinline__ float softplusf(float x) {
    return log1pf(expf(-fabsf(x))) + fmaxf(x, 0.0f);
}
__device__ __forceinline__ float sigmoidf(float x) {
    return 1.0f / (1.0f + expf(-x));
}
__device__ __forceinline__ void fma4(float4& a, float x, const float4 w) {
    a.x += x * w.x; a.y += x * w.y; a.z += x * w.z; a.w += x * w.w;
}
__device__ __forceinline__ float4 add4(float4 a, float4 b) {
    return make_float4(a.x + b.x, a.y + b.y, a.z + b.z, a.w + b.w);
}

// ---------------- SMEM layout for k_y (dynamic, bytes) ----------------
#define LDA 72            // bf16 leading dim (144B rows, conflict-free ldmatrix)
#define LDD 132           // fp32 D leading dim
#define SM_SIDX 0         // 128 ints
#define SM_NIDX 512
#define SM_SHS  1024      // 128 fp32
#define SM_SHQ  1536
#define SM_AHI  2048      // 128 x LDA bf16 = 18432 B
#define SM_ALO  (SM_AHI + 128 * LDA * 2)
#define SM_BHI  (SM_ALO + 128 * LDA * 2)     // B[n][k] = W3^T, 128 x LDA bf16
#define SM_BLO  (SM_BHI + 128 * LDA * 2)
#define SM_DBUF (SM_BLO + 128 * LDA * 2)     // 128 x LDD fp32 = 67584 B
#define SM_TOTAL (SM_DBUF + 128 * LDD * 4)   // 143360 B

// ---------------- kernels ----------------
__global__ void k_init() {
    int t = threadIdx.x;
    if (t < DOUT) { g_colsum[t] = 0.f; g_colsq[t] = 0.f; }
    if (t < ELEM) { g_s2[t] = 0.f; g_q2[t] = 0.f; }
}

__global__ void k_rowptr(const int* __restrict__ sidx) {
    int a = blockIdx.x * blockDim.x + threadIdx.x;
    if (a > NATOMS) return;
    int lo = 0, hi = NEDGES;
    while (lo < hi) {
        int mid = (lo + hi) >> 1;
        if (sidx[mid] < a) lo = mid + 1; else hi = mid;
    }
    g_rowptr[a] = lo;
}

// P1 = atom @ W[0:64] + b ;  P2 = atom @ W[64:128]
__global__ void __launch_bounds__(256) k_precompute(const float* __restrict__ atom,
                                                    const float* __restrict__ W,
                                                    const float* __restrict__ bias) {
    __shared__ float sW[64][DOUT];
    __shared__ float sAt[32][ELEM];
    const int tid = threadIdx.x;
    const int ab = blockIdx.x * 32;
    const int nvalid = min(32, NATOMS - ab);

    #pragma unroll
    for (int p = 0; p < 2; p++) {
        int i4 = tid + p * 256;
        int a = i4 >> 4, kv = i4 & 15;
        float4 v = make_float4(0.f, 0.f, 0.f, 0.f);
        if (a < nvalid) v = *(const float4*)(atom + (size_t)(ab + a) * ELEM + kv * 4);
        *(float4*)&sAt[a][kv * 4] = v;
    }

    const int a  = tid >> 3;
    const int ob = (tid & 7) * 16;

    for (int phase = 0; phase < 2; phase++) {
        __syncthreads();
        #pragma unroll
        for (int p = 0; p < 8; p++) {
            int i4 = tid + p * 256;
            int k = i4 >> 5, j4 = i4 & 31;
            *(float4*)&sW[k][j4 * 4] =
                *(const float4*)(W + (size_t)(phase * 64 + k) * DOUT + j4 * 4);
        }
        __syncthreads();

        float4 acc[4];
        #pragma unroll
        for (int q = 0; q < 4; q++) acc[q] = make_float4(0.f, 0.f, 0.f, 0.f);
        #pragma unroll 8
        for (int k = 0; k < 64; k++) {
            float x = sAt[a][k];
            #pragma unroll
            for (int q = 0; q < 4; q++) fma4(acc[q], x, *(float4*)&sW[k][ob + q * 4]);
        }
        if (a < nvalid) {
            float* dst = (phase == 0 ? g_P1 : g_P2) + (size_t)(ab + a) * DOUT + ob;
            #pragma unroll
            for (int q = 0; q < 4; q++) {
                float4 v = acc[q];
                if (phase == 0) v = add4(v, *(const float4*)(bias + ob + q * 4));
                *(float4*)(dst + q * 4) = v;
            }
        }
    }
}

// Pass 1 (HMMA): per 128-edge tile, G = nbr @ W3 via bf16 hi/lo split
// (3 passes: Ah*Bh + Ah*Bl + Al*Bh), y = G + P1[self] + P2[nbr]; store Y fp16,
// accumulate BN1 column stats. Persistent grid; W3 staged once per CTA.
__global__ void __launch_bounds__(256) k_y_mma(const float* __restrict__ nbr,
                                               const int* __restrict__ sidx,
                                               const int* __restrict__ nidx,
                                               const float* __restrict__ W) {
    extern __shared__ char sm[];
    __nv_bfloat16* sAhi = (__nv_bfloat16*)(sm + SM_AHI);
    __nv_bfloat16* sAlo = (__nv_bfloat16*)(sm + SM_ALO);
    __nv_bfloat16* sBhi = (__nv_bfloat16*)(sm + SM_BHI);
    __nv_bfloat16* sBlo = (__nv_bfloat16*)(sm + SM_BLO);
    float*         dbuf = (float*)(sm + SM_DBUF);
    int*   s_sidx = (int*)(sm + SM_SIDX);
    int*   s_nidx = (int*)(sm + SM_NIDX);
    float* shS    = (float*)(sm + SM_SHS);
    float* shQ    = (float*)(sm + SM_SHQ);

    const int tid = threadIdx.x;
    const int wid = tid >> 5;
    const int wm  = wid >> 1;      // 0..3 -> rows wm*32
    const int wn  = wid & 1;       // 0..1 -> cols wn*64

    if (tid < 128) { shS[tid] = 0.f; shQ[tid] = 0.f; }

    // Stage B = W3^T hi/lo: B[n][k] = W[(128+k)*128 + n]
    for (int p = 0; p < 32; p++) {
        int idx = p * 256 + tid;           // 8192 elems
        int k = idx >> 7, n = idx & 127;   // coalesced over n
        float v = W[(size_t)(128 + k) * DOUT + n];
        __nv_bfloat16 h = __float2bfloat16(v);
        sBhi[n * LDA + k] = h;
        sBlo[n * LDA + k] = __float2bfloat16(v - __bfloat162float(h));
    }
    __syncthreads();

    const int j2 = tid & 63;   // epilogue: column pair 2*j2, 2*j2+1
    const int rg = tid >> 6;   // epilogue: row group (32 rows)

    for (int t = blockIdx.x; t < NTILES; t += gridDim.x) {
        const int eb = t * 128;

        // ---- stage A tile: 128 edges x 64 feats fp32 -> bf16 hi/lo ----
        #pragma unroll
        for (int p = 0; p < 8; p++) {
            int i4 = tid + p * 256;              // 2048 float4s
            int row = i4 >> 4, kv = i4 & 15;     // coalesced
            float4 v = *(const float4*)(nbr + (size_t)(eb + row) * ELEM + kv * 4);
            __nv_bfloat16 h0 = __float2bfloat16(v.x), h1 = __float2bfloat16(v.y),
                          h2 = __float2bfloat16(v.z), h3 = __float2bfloat16(v.w);
            __nv_bfloat162 hh0; hh0.x = h0; hh0.y = h1;
            __nv_bfloat162 hh1; hh1.x = h2; hh1.y = h3;
            __nv_bfloat162 ll0;
            ll0.x = __float2bfloat16(v.x - __bfloat162float(h0));
            ll0.y = __float2bfloat16(v.y - __bfloat162float(h1));
            __nv_bfloat162 ll1;
            ll1.x = __float2bfloat16(v.z - __bfloat162float(h2));
            ll1.y = __float2bfloat16(v.w - __bfloat162float(h3));
            int o = row * LDA + kv * 4;
            *(__nv_bfloat162*)(sAhi + o)     = hh0;
            *(__nv_bfloat162*)(sAhi + o + 2) = hh1;
            *(__nv_bfloat162*)(sAlo + o)     = ll0;
            *(__nv_bfloat162*)(sAlo + o + 2) = ll1;
        }
        if (tid < 128) {
            s_sidx[tid] = sidx[eb + tid];
            s_nidx[tid] = nidx[eb + tid];
        }
        __syncthreads();   // A ready; prev epilogue done with dbuf

        // ---- MMA: acc = Ah*Bh + Ah*Bl + Al*Bh ----
        wmma::fragment<wmma::accumulator, 16, 16, 16, float> acc[2][4];
        #pragma unroll
        for (int i = 0; i < 2; i++)
            #pragma unroll
            for (int j = 0; j < 4; j++)
                wmma::fill_fragment(acc[i][j], 0.0f);

        #pragma unroll
        for (int pass = 0; pass < 3; pass++) {
            const __nv_bfloat16* Ab = (pass == 2) ? sAlo : sAhi;
            const __nv_bfloat16* Bb = (pass == 1) ? sBlo : sBhi;
            #pragma unroll
            for (int k = 0; k < 4; k++) {
                wmma::fragment<wmma::matrix_a, 16, 16, 16, __nv_bfloat16, wmma::row_major> af[2];
                #pragma unroll
                for (int i = 0; i < 2; i++)
                    wmma::load_matrix_sync(af[i], Ab + (wm * 32 + i * 16) * LDA + k * 16, LDA);
                wmma::fragment<wmma::matrix_b, 16, 16, 16, __nv_bfloat16, wmma::col_major> bf[4];
                #pragma unroll
                for (int j = 0; j < 4; j++)
                    wmma::load_matrix_sync(bf[j], Bb + (wn * 64 + j * 16) * LDA + k * 16, LDA);
                #pragma unroll
                for (int i = 0; i < 2; i++)
                    #pragma unroll
                    for (int j = 0; j < 4; j++)
                        wmma::mma_sync(acc[i][j], af[i], bf[j], acc[i][j]);
            }
        }
        #pragma unroll
        for (int i = 0; i < 2; i++)
            #pragma unroll
            for (int j = 0; j < 4; j++)
                wmma::store_matrix_sync(dbuf + (wm * 32 + i * 16) * LDD + wn * 64 + j * 16,
                                        acc[i][j], LDD, wmma::mem_row_major);
        __syncthreads();   // dbuf ready

        // ---- epilogue: y += P1[self] + P2[nbr]; stats; store fp16 ----
        float cs0 = 0.f, cq0 = 0.f, cs1 = 0.f, cq1 = 0.f;
        #pragma unroll 4
        for (int r = 0; r < 32; r++) {
            int row = rg * 32 + r;
            float2 y = *(float2*)&dbuf[row * LDD + 2 * j2];
            int s = s_sidx[row], n = s_nidx[row];
            float2 p1 = *(const float2*)&g_P1[(size_t)s * DOUT + 2 * j2];
            float2 p2 = *(const float2*)&g_P2[(size_t)n * DOUT + 2 * j2];
            y.x += p1.x + p2.x;
            y.y += p1.y + p2.y;
            cs0 += y.x; cq0 += y.x * y.x;
            cs1 += y.y; cq1 += y.y * y.y;
            __half2 hy = __floats2half2_rn(y.x, y.y);
            *(__half2*)&g_Yh[(size_t)(eb + row) * DOUT + 2 * j2] = hy;
        }
        atomicAdd(&shS[2 * j2],     cs0);
        atomicAdd(&shQ[2 * j2],     cq0);
        atomicAdd(&shS[2 * j2 + 1], cs1);
        atomicAdd(&shQ[2 * j2 + 1], cq1);
        __syncthreads();   // epilogue done before next A overwrite / dbuf reuse
    }

    if (tid < 128) {
        atomicAdd(&g_colsum[tid], shS[tid]);
        atomicAdd(&g_colsq[tid],  shQ[tid]);
    }
}

__global__ void k_bn1fin(const float* __restrict__ gamma, const float* __restrict__ beta) {
    int j = threadIdx.x;
    float mean = g_colsum[j] * (1.0f / NEDGES);
    float var  = g_colsq[j] * (1.0f / NEDGES) - mean * mean;
    float aa = gamma[j] * rsqrtf(var + BN_EPS);
    g_a1[j] = aa;
    g_c1[j] = beta[j] - mean * aa;
}

// Pass 2: BN1 + sigmoid*softplus + deterministic CSR segment sum.
// blockDim (32,8): lane j2 handles column pair (2*j2, 2*j2+1).
__global__ void __launch_bounds__(256) k_msg() {
    const int j2 = threadIdx.x;
    const int a  = blockIdx.x * 8 + threadIdx.y;
    if (a >= NATOMS) return;
    const float a1f0 = g_a1[2*j2],      c1f0 = g_c1[2*j2];
    const float a1f1 = g_a1[2*j2+1],    c1f1 = g_c1[2*j2+1];
    const float a1c0 = g_a1[64+2*j2],   c1c0 = g_c1[64+2*j2];
    const float a1c1 = g_a1[64+2*j2+1], c1c1 = g_c1[64+2*j2+1];
    const int e0 = g_rowptr[a];
    const int e1 = g_rowptr[a + 1];
    float s0 = 0.f, s1 = 0.f;
    const __half2* Y2 = (const __half2*)g_Yh;
    for (int e = e0; e < e1; e++) {
        __half2 hf = Y2[(size_t)e * 64 + j2];
        __half2 hc = Y2[(size_t)e * 64 + 32 + j2];
        float yf, yc;
        yf = __low2float(hf)  * a1f0 + c1f0; yc = __low2float(hc)  * a1c0 + c1c0;
        s0 += sigmoidf(yf) * softplusf(yc);
        yf = __high2float(hf) * a1f1 + c1f1; yc = __high2float(hc) * a1c1 + c1c1;
        s1 += sigmoidf(yf) * softplusf(yc);
    }
    g_sumed[(size_t)a * ELEM + 2 * j2]     = s0;
    g_sumed[(size_t)a * ELEM + 2 * j2 + 1] = s1;
}

__global__ void k_bn2stats() {
    const int tid = blockIdx.x * blockDim.x + threadIdx.x;
    const int col = threadIdx.x & 63;
    const int stride = gridDim.x * blockDim.x;
    float s = 0.f, q = 0.f;
    for (int i = tid; i < NATOMS * ELEM; i += stride) {
        float v = g_sumed[i];
        s += v; q += v * v;
    }
    __shared__ float shS[ELEM], shQ[ELEM];
    if (threadIdx.x < ELEM) { shS[threadIdx.x] = 0.f; shQ[threadIdx.x] = 0.f; }
    __syncthreads();
    atomicAdd(&shS[col], s);
    atomicAdd(&shQ[col], q);
    __syncthreads();
    if (threadIdx.x < ELEM) {
        atomicAdd(&g_s2[threadIdx.x], shS[threadIdx.x]);
        atomicAdd(&g_q2[threadIdx.x], shQ[threadIdx.x]);
    }
}

__global__ void k_bn2fin(const float* __restrict__ gamma, const float* __restrict__ beta) {
    int j = threadIdx.x;
    float mean = g_s2[j] * (1.0f / NATOMS);
    float var  = g_q2[j] * (1.0f / NATOMS) - mean * mean;
    float aa = gamma[j] * rsqrtf(var + BN_EPS);
    g_a2[j] = aa;
    g_c2[j] = beta[j] - mean * aa;
}

__global__ void k_final(const float* __restrict__ atom, float* __restrict__ out) {
    int i = blockIdx.x * blockDim.x + threadIdx.x;
    if (i >= NATOMS * ELEM) return;
    int j = i & 63;
    float v = atom[i] + g_sumed[i] * g_a2[j] + g_c2[j];
    out[i] = softplusf(v);
}

// ---------------- launch ----------------
extern "C" void kernel_launch(void* const* d_in, const int* in_sizes, int n_in,
                              void* d_out, int out_size) {
    const float* atom = (const float*)d_in[0];
    const float* nbr  = (const float*)d_in[1];
    const int*   sidx = (const int*)d_in[2];
    const int*   nidx = (const int*)d_in[3];
    const float* W    = (const float*)d_in[4];
    const float* bias = (const float*)d_in[5];
    const float* g1   = (const float*)d_in[6];
    const float* be1  = (const float*)d_in[7];
    const float* g2   = (const float*)d_in[8];
    const float* be2  = (const float*)d_in[9];
    float* out = (float*)d_out;

    cudaFuncSetAttribute(k_y_mma, cudaFuncAttributeMaxDynamicSharedMemorySize, SM_TOTAL);

    k_init<<<1, 128>>>();
    k_precompute<<<(NATOMS + 31) / 32, 256>>>(atom, W, bias);
    k_rowptr<<<(NATOMS + 1 + 255) / 256, 256>>>(sidx);
    k_y_mma<<<GRID_Y, 256, SM_TOTAL>>>(nbr, sidx, nidx, W);
    k_bn1fin<<<1, DOUT>>>(g1, be1);
    dim3 mblk(32, 8);
    k_msg<<<(NATOMS + 7) / 8, mblk>>>();
    k_bn2stats<<<128, 256>>>();
    k_bn2fin<<<1, ELEM>>>(g2, be2);
    k_final<<<(NATOMS * ELEM + 255) / 256, 256>>>(atom, out);
}

// round 4
// speedup vs baseline: 2.9672x; 2.0741x over previous
#include <cuda_runtime.h>
#include <cuda_bf16.h>
#include <cuda_fp16.h>
#include <mma.h>
#include <math.h>
#include <stdint.h>

using namespace nvcuda;

#define NATOMS 50000
#define NEDGES 800000
#define ELEM   64
#define DOUT   128
#define BN_EPS 1e-5f
#define NTILES (NEDGES / 128)     // 6250
#define GRID_Y 148                // persistent, 1 CTA/SM

// ---------------- scratch (device globals; no allocation allowed) ----------------
__device__ float  g_P1[(size_t)NATOMS * DOUT];   // atom @ W1 + b
__device__ float  g_P2[(size_t)NATOMS * DOUT];   // atom @ W2
__device__ __half g_Yh[(size_t)NEDGES * DOUT];   // pre-BN edge features, fp16
__device__ int    g_rowptr[NATOMS + 1];
__device__ float  g_colsum[DOUT];
__device__ float  g_colsq [DOUT];
__device__ float  g_a1[DOUT], g_c1[DOUT];
__device__ float  g_sumed[(size_t)NATOMS * ELEM];
__device__ float  g_s2[ELEM], g_q2[ELEM];
__device__ float  g_a2[ELEM], g_c2[ELEM];

// ---------------- helpers ----------------
__device__ __forceinline__ float softplusf(float x) {
    return log1pf(expf(-fabsf(x))) + fmaxf(x, 0.0f);
}
__device__ __forceinline__ float msg_gate(float yf, float yc) {
    // sigmoid(yf) * softplus(yc), fast-math paths (err ~2^-21, << fp16 storage err)
    float ef  = __expf(-yf);
    float sig = __fdividef(1.0f, 1.0f + ef);
    float ec  = __expf(-fabsf(yc));
    float sp  = __logf(1.0f + ec) + fmaxf(yc, 0.0f);
    return sig * sp;
}
__device__ __forceinline__ void fma4(float4& a, float x, const float4 w) {
    a.x += x * w.x; a.y += x * w.y; a.z += x * w.z; a.w += x * w.w;
}
__device__ __forceinline__ float4 add4(float4 a, float4 b) {
    return make_float4(a.x + b.x, a.y + b.y, a.z + b.z, a.w + b.w);
}
__device__ __forceinline__ uint32_t smem_u32(const void* p) {
    uint32_t a;
    asm("{ .reg .u64 t; cvta.to.shared.u64 t, %1; cvt.u32.u64 %0, t; }" : "=r"(a) : "l"(p));
    return a;
}
#define CP_ASYNC16(dst_u32, src_ptr) \
    asm volatile("cp.async.cg.shared.global [%0], [%1], 16;" :: "r"(dst_u32), "l"(src_ptr))
#define CP_COMMIT() asm volatile("cp.async.commit_group;" ::: "memory")
#define CP_WAIT1()  asm volatile("cp.async.wait_group 1;" ::: "memory")

// ---------------- SMEM layout for k_y (dynamic, bytes) ----------------
#define LDA 72            // bf16 leading dim
#define LDD 132           // fp32 D leading dim
#define SM_SHS   0        // 128 fp32
#define SM_SHQ   512
#define SM_IDX   1024     // 2 stages x (128 sidx + 128 nidx) ints = 2 x 1024 B
#define SM_STAGE 3072     // 2 stages x 128x64 fp32 = 2 x 32768 B
#define SM_AHI   68608    // 128 x LDA bf16 = 18432 B
#define SM_ALO   87040
#define SM_BHI   105472   // B[n][k] = W3^T
#define SM_BLO   123904
#define SM_DBUF  142336   // 128 x LDD fp32 = 67584 B
#define SM_TOTAL 209920

// ---------------- kernels ----------------
__global__ void k_init() {
    int t = threadIdx.x;
    if (t < DOUT) { g_colsum[t] = 0.f; g_colsq[t] = 0.f; }
    if (t < ELEM) { g_s2[t] = 0.f; g_q2[t] = 0.f; }
}

__global__ void k_rowptr(const int* __restrict__ sidx) {
    int a = blockIdx.x * blockDim.x + threadIdx.x;
    if (a > NATOMS) return;
    int lo = 0, hi = NEDGES;
    while (lo < hi) {
        int mid = (lo + hi) >> 1;
        if (sidx[mid] < a) lo = mid + 1; else hi = mid;
    }
    g_rowptr[a] = lo;
}

// P1 = atom @ W[0:64] + b ;  P2 = atom @ W[64:128].  128 atoms per block.
#define PRE_LDAT 68
#define PRE_SW   (64 * DOUT)                    // floats
#define PRE_SMEM ((PRE_SW + 128 * PRE_LDAT) * 4)  // 32768 + 34816 = 67584 B
__global__ void __launch_bounds__(256) k_precompute(const float* __restrict__ atom,
                                                    const float* __restrict__ W,
                                                    const float* __restrict__ bias) {
    extern __shared__ float psm[];
    float* sW  = psm;                  // [64][128]
    float* sAt = psm + PRE_SW;         // [128][PRE_LDAT]
    const int tid = threadIdx.x;
    const int ab = blockIdx.x * 128;
    const int nvalid = min(128, NATOMS - ab);

    #pragma unroll
    for (int p = 0; p < 8; p++) {                  // 128*64 floats = 2048 float4
        int i4 = tid + p * 256;
        int a = i4 >> 4, kv = i4 & 15;
        float4 v = make_float4(0.f, 0.f, 0.f, 0.f);
        if (a < nvalid) v = *(const float4*)(atom + (size_t)(ab + a) * ELEM + kv * 4);
        *(float4*)&sAt[a * PRE_LDAT + kv * 4] = v;
    }

    const int a  = tid >> 1;           // 128 atoms, 2 threads each
    const int ob = (tid & 1) * 64;     // 64 output cols per thread

    for (int phase = 0; phase < 2; phase++) {
        __syncthreads();
        #pragma unroll
        for (int p = 0; p < 8; p++) {              // 64*128 floats = 2048 float4
            int i4 = tid + p * 256;
            int k = i4 >> 5, j4 = i4 & 31;
            *(float4*)&sW[k * DOUT + j4 * 4] =
                *(const float4*)(W + (size_t)(phase * 64 + k) * DOUT + j4 * 4);
        }
        __syncthreads();

        float4 acc[16];
        #pragma unroll
        for (int q = 0; q < 16; q++) acc[q] = make_float4(0.f, 0.f, 0.f, 0.f);
        #pragma unroll 4
        for (int k = 0; k < 64; k++) {
            float x = sAt[a * PRE_LDAT + k];
            #pragma unroll
            for (int q = 0; q < 16; q++) fma4(acc[q], x, *(float4*)&sW[k * DOUT + ob + q * 4]);
        }
        if (a < nvalid) {
            float* dst = (phase == 0 ? g_P1 : g_P2) + (size_t)(ab + a) * DOUT + ob;
            #pragma unroll
            for (int q = 0; q < 16; q++) {
                float4 v = acc[q];
                if (phase == 0) v = add4(v, *(const float4*)(bias + ob + q * 4));
                *(float4*)(dst + q * 4) = v;
            }
        }
    }
}

// Pass 1 (HMMA, cp.async-pipelined): per 128-edge tile, G = nbr @ W3 via bf16
// hi/lo split; y = G + P1[self] + P2[nbr]; store Y fp16, accumulate BN1 stats.
__global__ void __launch_bounds__(256) k_y_mma(const float* __restrict__ nbr,
                                               const int* __restrict__ sidx,
                                               const int* __restrict__ nidx,
                                               const float* __restrict__ W) {
    extern __shared__ char sm[];
    const uint32_t smb = smem_u32(sm);
    __nv_bfloat16* sAhi = (__nv_bfloat16*)(sm + SM_AHI);
    __nv_bfloat16* sAlo = (__nv_bfloat16*)(sm + SM_ALO);
    __nv_bfloat16* sBhi = (__nv_bfloat16*)(sm + SM_BHI);
    __nv_bfloat16* sBlo = (__nv_bfloat16*)(sm + SM_BLO);
    float*         dbuf = (float*)(sm + SM_DBUF);
    float*         shS  = (float*)(sm + SM_SHS);
    float*         shQ  = (float*)(sm + SM_SHQ);

    const int tid = threadIdx.x;
    const int wid = tid >> 5;
    const int wm  = wid >> 1;
    const int wn  = wid & 1;

    if (tid < 128) { shS[tid] = 0.f; shQ[tid] = 0.f; }

    // Stage B = W3^T hi/lo: B[n][k] = W[(128+k)*128 + n]
    for (int p = 0; p < 32; p++) {
        int idx = p * 256 + tid;
        int k = idx >> 7, n = idx & 127;
        float v = W[(size_t)(128 + k) * DOUT + n];
        __nv_bfloat16 h = __float2bfloat16(v);
        sBhi[n * LDA + k] = h;
        sBlo[n * LDA + k] = __float2bfloat16(v - __bfloat162float(h));
    }

    // prologue: prefetch first tile into stage 0
    int t0 = blockIdx.x;
    {
        uint32_t dstA = smb + SM_STAGE;
        const float* srcA = nbr + (size_t)t0 * 128 * ELEM;
        #pragma unroll
        for (int p = 0; p < 8; p++) {
            int i4 = tid + p * 256;
            CP_ASYNC16(dstA + i4 * 16, srcA + i4 * 4);
        }
        if (tid < 32)      CP_ASYNC16(smb + SM_IDX + tid * 16, sidx + t0 * 128 + tid * 4);
        else if (tid < 64) CP_ASYNC16(smb + SM_IDX + 512 + (tid - 32) * 16, nidx + t0 * 128 + (tid - 32) * 4);
    }
    CP_COMMIT();

    const int j2 = tid & 63;   // epilogue: column pair
    const int rg = tid >> 6;   // epilogue: row group
    int buf = 0;

    for (int t = t0; t < NTILES; t += GRID_Y) {
        const int eb = t * 128;
        const int tn = t + GRID_Y;

        // prefetch next tile into other stage
        if (tn < NTILES) {
            uint32_t dstA = smb + SM_STAGE + (buf ^ 1) * 32768;
            const float* srcA = nbr + (size_t)tn * 128 * ELEM;
            #pragma unroll
            for (int p = 0; p < 8; p++) {
                int i4 = tid + p * 256;
                CP_ASYNC16(dstA + i4 * 16, srcA + i4 * 4);
            }
            uint32_t dstI = smb + SM_IDX + (buf ^ 1) * 1024;
            if (tid < 32)      CP_ASYNC16(dstI + tid * 16, sidx + tn * 128 + tid * 4);
            else if (tid < 64) CP_ASYNC16(dstI + 512 + (tid - 32) * 16, nidx + tn * 128 + (tid - 32) * 4);
        }
        CP_COMMIT();
        CP_WAIT1();            // stage[buf] complete (newest group may still fly)
        __syncthreads();

        // ---- convert staged fp32 A -> bf16 hi/lo ----
        const float* stg = (const float*)(sm + SM_STAGE + buf * 32768);
        #pragma unroll
        for (int p = 0; p < 8; p++) {
            int i4 = tid + p * 256;
            int row = i4 >> 4, kv = i4 & 15;
            float4 v = *(const float4*)(stg + i4 * 4);
            __nv_bfloat16 h0 = __float2bfloat16(v.x), h1 = __float2bfloat16(v.y),
                          h2 = __float2bfloat16(v.z), h3 = __float2bfloat16(v.w);
            __nv_bfloat162 hh0; hh0.x = h0; hh0.y = h1;
            __nv_bfloat162 hh1; hh1.x = h2; hh1.y = h3;
            __nv_bfloat162 ll0;
            ll0.x = __float2bfloat16(v.x - __bfloat162float(h0));
            ll0.y = __float2bfloat16(v.y - __bfloat162float(h1));
            __nv_bfloat162 ll1;
            ll1.x = __float2bfloat16(v.z - __bfloat162float(h2));
            ll1.y = __float2bfloat16(v.w - __bfloat162float(h3));
            int o = row * LDA + kv * 4;
            *(__nv_bfloat162*)(sAhi + o)     = hh0;
            *(__nv_bfloat162*)(sAhi + o + 2) = hh1;
            *(__nv_bfloat162*)(sAlo + o)     = ll0;
            *(__nv_bfloat162*)(sAlo + o + 2) = ll1;
        }
        __syncthreads();

        // ---- MMA: acc = Ah*Bh + Ah*Bl + Al*Bh  (shared frag loads per k) ----
        wmma::fragment<wmma::accumulator, 16, 16, 16, float> acc[2][4];
        #pragma unroll
        for (int i = 0; i < 2; i++)
            #pragma unroll
            for (int j = 0; j < 4; j++)
                wmma::fill_fragment(acc[i][j], 0.0f);

        #pragma unroll
        for (int k = 0; k < 4; k++) {
            wmma::fragment<wmma::matrix_a, 16, 16, 16, __nv_bfloat16, wmma::row_major> ah[2], al[2];
            wmma::fragment<wmma::matrix_b, 16, 16, 16, __nv_bfloat16, wmma::col_major> bh[4], bl[4];
            #pragma unroll
            for (int i = 0; i < 2; i++)
                wmma::load_matrix_sync(ah[i], sAhi + (wm * 32 + i * 16) * LDA + k * 16, LDA);
            #pragma unroll
            for (int j = 0; j < 4; j++)
                wmma::load_matrix_sync(bh[j], sBhi + (wn * 64 + j * 16) * LDA + k * 16, LDA);
            #pragma unroll
            for (int i = 0; i < 2; i++)
                #pragma unroll
                for (int j = 0; j < 4; j++)
                    wmma::mma_sync(acc[i][j], ah[i], bh[j], acc[i][j]);
            #pragma unroll
            for (int j = 0; j < 4; j++)
                wmma::load_matrix_sync(bl[j], sBlo + (wn * 64 + j * 16) * LDA + k * 16, LDA);
            #pragma unroll
            for (int i = 0; i < 2; i++)
                #pragma unroll
                for (int j = 0; j < 4; j++)
                    wmma::mma_sync(acc[i][j], ah[i], bl[j], acc[i][j]);
            #pragma unroll
            for (int i = 0; i < 2; i++)
                wmma::load_matrix_sync(al[i], sAlo + (wm * 32 + i * 16) * LDA + k * 16, LDA);
            #pragma unroll
            for (int i = 0; i < 2; i++)
                #pragma unroll
                for (int j = 0; j < 4; j++)
                    wmma::mma_sync(acc[i][j], al[i], bh[j], acc[i][j]);
        }
        #pragma unroll
        for (int i = 0; i < 2; i++)
            #pragma unroll
            for (int j = 0; j < 4; j++)
                wmma::store_matrix_sync(dbuf + (wm * 32 + i * 16) * LDD + wn * 64 + j * 16,
                                        acc[i][j], LDD, wmma::mem_row_major);
        __syncthreads();

        // ---- epilogue: y += P1[self] + P2[nbr]; stats; store fp16 ----
        const int* s_sidx = (const int*)(sm + SM_IDX + buf * 1024);
        const int* s_nidx = s_sidx + 128;
        float cs0 = 0.f, cq0 = 0.f, cs1 = 0.f, cq1 = 0.f;
        #pragma unroll 8
        for (int r = 0; r < 32; r++) {
            int row = rg * 32 + r;
            float2 y = *(float2*)&dbuf[row * LDD + 2 * j2];
            int s = s_sidx[row], n = s_nidx[row];
            float2 p1 = __ldg((const float2*)&g_P1[(size_t)s * DOUT + 2 * j2]);
            float2 p2 = __ldg((const float2*)&g_P2[(size_t)n * DOUT + 2 * j2]);
            y.x += p1.x + p2.x;
            y.y += p1.y + p2.y;
            cs0 += y.x; cq0 += y.x * y.x;
            cs1 += y.y; cq1 += y.y * y.y;
            *(__half2*)&g_Yh[(size_t)(eb + row) * DOUT + 2 * j2] = __floats2half2_rn(y.x, y.y);
        }
        atomicAdd(&shS[2 * j2],     cs0);
        atomicAdd(&shQ[2 * j2],     cq0);
        atomicAdd(&shS[2 * j2 + 1], cs1);
        atomicAdd(&shQ[2 * j2 + 1], cq1);
        buf ^= 1;
        __syncthreads();   // idx[buf] still read above; protect against next prefetch
    }

    if (tid < 128) {
        atomicAdd(&g_colsum[tid], shS[tid]);
        atomicAdd(&g_colsq[tid],  shQ[tid]);
    }
}

__global__ void k_bn1fin(const float* __restrict__ gamma, const float* __restrict__ beta) {
    int j = threadIdx.x;
    float mean = g_colsum[j] * (1.0f / NEDGES);
    float var  = g_colsq[j] * (1.0f / NEDGES) - mean * mean;
    float aa = gamma[j] * rsqrtf(var + BN_EPS);
    g_a1[j] = aa;
    g_c1[j] = beta[j] - mean * aa;
}

// Pass 2: BN1 + gate + deterministic CSR segment sum. Warp per atom:
// lanes 0-15 even edges, 16-31 odd edges; each lane 4 columns (float2 loads).
__global__ void __launch_bounds__(256) k_msg() {
    const int lane = threadIdx.x;         // 32
    const int a = blockIdx.x * 8 + threadIdx.y;
    if (a >= NATOMS) return;
    const int half = lane >> 4;
    const int j4 = lane & 15;             // columns 4*j4 .. 4*j4+3

    float a1f[4], c1f[4], a1c[4], c1c[4];
    #pragma unroll
    for (int q = 0; q < 4; q++) {
        int j = 4 * j4 + q;
        a1f[q] = g_a1[j];      c1f[q] = g_c1[j];
        a1c[q] = g_a1[64 + j]; c1c[q] = g_c1[64 + j];
    }

    const int e0 = g_rowptr[a], e1 = g_rowptr[a + 1];
    float s[4] = {0.f, 0.f, 0.f, 0.f};
    const char* Yb = (const char*)g_Yh;

    for (int e = e0 + half; e < e1; e += 2) {
        float2 fv = *(const float2*)(Yb + (size_t)e * 256 + j4 * 8);
        float2 cv = *(const float2*)(Yb + (size_t)e * 256 + 128 + j4 * 8);
        __half2 f01 = *(__half2*)&fv.x, f23 = *(__half2*)&fv.y;
        __half2 c01 = *(__half2*)&cv.x, c23 = *(__half2*)&cv.y;
        float yf, yc;
        yf = __low2float(f01)  * a1f[0] + c1f[0]; yc = __low2float(c01)  * a1c[0] + c1c[0];
        s[0] += msg_gate(yf, yc);
        yf = __high2float(f01) * a1f[1] + c1f[1]; yc = __high2float(c01) * a1c[1] + c1c[1];
        s[1] += msg_gate(yf, yc);
        yf = __low2float(f23)  * a1f[2] + c1f[2]; yc = __low2float(c23)  * a1c[2] + c1c[2];
        s[2] += msg_gate(yf, yc);
        yf = __high2float(f23) * a1f[3] + c1f[3]; yc = __high2float(c23) * a1c[3] + c1c[3];
        s[3] += msg_gate(yf, yc);
    }
    #pragma unroll
    for (int q = 0; q < 4; q++)
        s[q] += __shfl_down_sync(0xffffffff, s[q], 16);
    if (half == 0) {
        float4 st = make_float4(s[0], s[1], s[2], s[3]);
        *(float4*)&g_sumed[(size_t)a * ELEM + j4 * 4] = st;
    }
}

__global__ void k_bn2stats() {
    const int tid = blockIdx.x * blockDim.x + threadIdx.x;
    const int col = threadIdx.x & 63;
    const int stride = gridDim.x * blockDim.x;
    float s = 0.f, q = 0.f;
    for (int i = tid; i < NATOMS * ELEM; i += stride) {
        float v = g_sumed[i];
        s += v; q += v * v;
    }
    __shared__ float shS[ELEM], shQ[ELEM];
    if (threadIdx.x < ELEM) { shS[threadIdx.x] = 0.f; shQ[threadIdx.x] = 0.f; }
    __syncthreads();
    atomicAdd(&shS[col], s);
    atomicAdd(&shQ[col], q);
    __syncthreads();
    if (threadIdx.x < ELEM) {
        atomicAdd(&g_s2[threadIdx.x], shS[threadIdx.x]);
        atomicAdd(&g_q2[threadIdx.x], shQ[threadIdx.x]);
    }
}

__global__ void k_bn2fin(const float* __restrict__ gamma, const float* __restrict__ beta) {
    int j = threadIdx.x;
    float mean = g_s2[j] * (1.0f / NATOMS);
    float var  = g_q2[j] * (1.0f / NATOMS) - mean * mean;
    float aa = gamma[j] * rsqrtf(var + BN_EPS);
    g_a2[j] = aa;
    g_c2[j] = beta[j] - mean * aa;
}

__global__ void k_final(const float* __restrict__ atom, float* __restrict__ out) {
    int i = blockIdx.x * blockDim.x + threadIdx.x;
    if (i >= NATOMS * ELEM) return;
    int j = i & 63;
    float v = atom[i] + g_sumed[i] * g_a2[j] + g_c2[j];
    out[i] = softplusf(v);
}

// ---------------- launch ----------------
extern "C" void kernel_launch(void* const* d_in, const int* in_sizes, int n_in,
                              void* d_out, int out_size) {
    const float* atom = (const float*)d_in[0];
    const float* nbr  = (const float*)d_in[1];
    const int*   sidx = (const int*)d_in[2];
    const int*   nidx = (const int*)d_in[3];
    const float* W    = (const float*)d_in[4];
    const float* bias = (const float*)d_in[5];
    const float* g1   = (const float*)d_in[6];
    const float* be1  = (const float*)d_in[7];
    const float* g2   = (const float*)d_in[8];
    const float* be2  = (const float*)d_in[9];
    float* out = (float*)d_out;

    cudaFuncSetAttribute(k_y_mma, cudaFuncAttributeMaxDynamicSharedMemorySize, SM_TOTAL);
    cudaFuncSetAttribute(k_precompute, cudaFuncAttributeMaxDynamicSharedMemorySize, PRE_SMEM);

    k_init<<<1, 128>>>();
    k_precompute<<<(NATOMS + 127) / 128, 256, PRE_SMEM>>>(atom, W, bias);
    k_rowptr<<<(NATOMS + 1 + 255) / 256, 256>>>(sidx);
    k_y_mma<<<GRID_Y, 256, SM_TOTAL>>>(nbr, sidx, nidx, W);
    k_bn1fin<<<1, DOUT>>>(g1, be1);
    dim3 mblk(32, 8);
    k_msg<<<(NATOMS + 7) / 8, mblk>>>();
    k_bn2stats<<<128, 256>>>();
    k_bn2fin<<<1, ELEM>>>(g2, be2);
    k_final<<<(NATOMS * ELEM + 255) / 256, 256>>>(atom, out);
}

// round 5
// speedup vs baseline: 3.3850x; 1.1408x over previous
#include <cuda_runtime.h>
#include <cuda_bf16.h>
#include <cuda_fp16.h>
#include <mma.h>
#include <math.h>
#include <stdint.h>

using namespace nvcuda;

#define NATOMS 50000
#define NEDGES 800000
#define ELEM   64
#define DOUT   128
#define BN_EPS 1e-5f
#define NTILES (NEDGES / 128)     // 6250
#define GRID_Y 296                // persistent, 2 CTAs/SM

// ---------------- scratch (device globals; no allocation allowed) ----------------
__device__ float  g_P1[(size_t)NATOMS * DOUT];   // atom @ W1 + b
__device__ float  g_P2[(size_t)NATOMS * DOUT];   // atom @ W2
__device__ __half g_Yh[(size_t)NEDGES * DOUT];   // pre-BN edge features, fp16
__device__ int    g_rowptr[NATOMS + 1];
__device__ float  g_colsum[DOUT];
__device__ float  g_colsq [DOUT];
__device__ float  g_a1[DOUT], g_c1[DOUT];
__device__ float  g_sumed[(size_t)NATOMS * ELEM];
__device__ float  g_s2[ELEM], g_q2[ELEM];
__device__ float  g_a2[ELEM], g_c2[ELEM];

// ---------------- helpers ----------------
__device__ __forceinline__ float softplusf(float x) {
    return log1pf(expf(-fabsf(x))) + fmaxf(x, 0.0f);
}
__device__ __forceinline__ float msg_gate(float yf, float yc) {
    float ef  = __expf(-yf);
    float sig = __fdividef(1.0f, 1.0f + ef);
    float ec  = __expf(-fabsf(yc));
    float sp  = __logf(1.0f + ec) + fmaxf(yc, 0.0f);
    return sig * sp;
}
__device__ __forceinline__ void fma4(float4& a, float x, const float4 w) {
    a.x += x * w.x; a.y += x * w.y; a.z += x * w.z; a.w += x * w.w;
}
__device__ __forceinline__ float4 add4(float4 a, float4 b) {
    return make_float4(a.x + b.x, a.y + b.y, a.z + b.z, a.w + b.w);
}

// ---------------- SMEM layout for k_y (dynamic, bytes) ----------------
#define LDA 72            // bf16 leading dim (elements)
#define LDH 68            // fp32 half-dbuf leading dim (elements)
#define SM_SHS   0        // 128 fp32
#define SM_SHQ   512
#define SM_SIDX  1024     // 128 ints
#define SM_NIDX  1536
#define SM_AHI   2048     // 128 x LDA bf16 = 18432 B
#define SM_ALO   20480
#define SM_BHI   38912    // B[n][k] = W3^T
#define SM_BLO   57344
#define SM_DBUF  75776    // 128 x LDH fp32 = 34816 B
#define SM_TOTAL 110592   // 108 KB -> 2 CTAs/SM

// ---------------- kernels ----------------
__global__ void k_init() {
    int t = threadIdx.x;
    if (t < DOUT) { g_colsum[t] = 0.f; g_colsq[t] = 0.f; }
    if (t < ELEM) { g_s2[t] = 0.f; g_q2[t] = 0.f; }
}

__global__ void k_rowptr(const int* __restrict__ sidx) {
    int a = blockIdx.x * blockDim.x + threadIdx.x;
    if (a > NATOMS) return;
    int lo = 0, hi = NEDGES;
    while (lo < hi) {
        int mid = (lo + hi) >> 1;
        if (sidx[mid] < a) lo = mid + 1; else hi = mid;
    }
    g_rowptr[a] = lo;
}

// P1 = atom @ W[0:64] + b ;  P2 = atom @ W[64:128].  128 atoms per block.
#define PRE_LDAT 68
#define PRE_SW   (64 * DOUT)
#define PRE_SMEM ((PRE_SW + 128 * PRE_LDAT) * 4)
__global__ void __launch_bounds__(256) k_precompute(const float* __restrict__ atom,
                                                    const float* __restrict__ W,
                                                    const float* __restrict__ bias) {
    extern __shared__ float psm[];
    float* sW  = psm;
    float* sAt = psm + PRE_SW;
    const int tid = threadIdx.x;
    const int ab = blockIdx.x * 128;
    const int nvalid = min(128, NATOMS - ab);

    #pragma unroll
    for (int p = 0; p < 8; p++) {
        int i4 = tid + p * 256;
        int a = i4 >> 4, kv = i4 & 15;
        float4 v = make_float4(0.f, 0.f, 0.f, 0.f);
        if (a < nvalid) v = *(const float4*)(atom + (size_t)(ab + a) * ELEM + kv * 4);
        *(float4*)&sAt[a * PRE_LDAT + kv * 4] = v;
    }

    const int a  = tid >> 1;
    const int ob = (tid & 1) * 64;

    for (int phase = 0; phase < 2; phase++) {
        __syncthreads();
        #pragma unroll
        for (int p = 0; p < 8; p++) {
            int i4 = tid + p * 256;
            int k = i4 >> 5, j4 = i4 & 31;
            *(float4*)&sW[k * DOUT + j4 * 4] =
                *(const float4*)(W + (size_t)(phase * 64 + k) * DOUT + j4 * 4);
        }
        __syncthreads();

        float4 acc[16];
        #pragma unroll
        for (int q = 0; q < 16; q++) acc[q] = make_float4(0.f, 0.f, 0.f, 0.f);
        #pragma unroll 4
        for (int k = 0; k < 64; k++) {
            float x = sAt[a * PRE_LDAT + k];
            #pragma unroll
            for (int q = 0; q < 16; q++) fma4(acc[q], x, *(float4*)&sW[k * DOUT + ob + q * 4]);
        }
        if (a < nvalid) {
            float* dst = (phase == 0 ? g_P1 : g_P2) + (size_t)(ab + a) * DOUT + ob;
            #pragma unroll
            for (int q = 0; q < 16; q++) {
                float4 v = acc[q];
                if (phase == 0) v = add4(v, *(const float4*)(bias + ob + q * 4));
                *(float4*)(dst + q * 4) = v;
            }
        }
    }
}

// Pass 1 (HMMA, 2 CTAs/SM): per 128-edge tile, G = nbr @ W3 via bf16 hi/lo
// split; y = G + P1[self] + P2[nbr]; store Y fp16 (streaming), BN1 stats.
__global__ void __launch_bounds__(256, 2) k_y_mma(const float* __restrict__ nbr,
                                                  const int* __restrict__ sidx,
                                                  const int* __restrict__ nidx,
                                                  const float* __restrict__ W) {
    extern __shared__ char sm[];
    __nv_bfloat16* sAhi = (__nv_bfloat16*)(sm + SM_AHI);
    __nv_bfloat16* sAlo = (__nv_bfloat16*)(sm + SM_ALO);
    __nv_bfloat16* sBhi = (__nv_bfloat16*)(sm + SM_BHI);
    __nv_bfloat16* sBlo = (__nv_bfloat16*)(sm + SM_BLO);
    float*         dbuf = (float*)(sm + SM_DBUF);
    float*         shS  = (float*)(sm + SM_SHS);
    float*         shQ  = (float*)(sm + SM_SHQ);
    int*           s_sidx = (int*)(sm + SM_SIDX);
    int*           s_nidx = (int*)(sm + SM_NIDX);

    const int tid = threadIdx.x;
    const int wid = tid >> 5;
    const int wm  = wid >> 1;
    const int wn  = wid & 1;

    if (tid < 128) { shS[tid] = 0.f; shQ[tid] = 0.f; }

    // Stage B = W3^T hi/lo: B[n][k] = W[(128+k)*128 + n]
    for (int p = 0; p < 32; p++) {
        int idx = p * 256 + tid;
        int k = idx >> 7, n = idx & 127;
        float v = W[(size_t)(128 + k) * DOUT + n];
        __nv_bfloat16 h = __float2bfloat16(v);
        sBhi[n * LDA + k] = h;
        sBlo[n * LDA + k] = __float2bfloat16(v - __bfloat162float(h));
    }
    __syncthreads();

    const int j2 = tid & 31;   // epilogue: column pair within a 64-col half
    const int rg = tid >> 5;   // epilogue: row group (16 rows)

    for (int t = blockIdx.x; t < NTILES; t += GRID_Y) {
        const int eb = t * 128;

        // ---- LDG A tile (8 independent float4/thread), convert, STS bf16 ----
        float4 v[8];
        #pragma unroll
        for (int p = 0; p < 8; p++)
            v[p] = __ldg((const float4*)(nbr + (size_t)eb * ELEM) + tid + p * 256);
        if (tid < 128) {
            s_sidx[tid] = __ldg(sidx + eb + tid);
            s_nidx[tid] = __ldg(nidx + eb + tid);
        }
        #pragma unroll
        for (int p = 0; p < 8; p++) {
            int i4 = tid + p * 256;
            int row = i4 >> 4, kv = i4 & 15;
            __nv_bfloat16 h0 = __float2bfloat16(v[p].x), h1 = __float2bfloat16(v[p].y),
                          h2 = __float2bfloat16(v[p].z), h3 = __float2bfloat16(v[p].w);
            __nv_bfloat162 hh0; hh0.x = h0; hh0.y = h1;
            __nv_bfloat162 hh1; hh1.x = h2; hh1.y = h3;
            __nv_bfloat162 ll0;
            ll0.x = __float2bfloat16(v[p].x - __bfloat162float(h0));
            ll0.y = __float2bfloat16(v[p].y - __bfloat162float(h1));
            __nv_bfloat162 ll1;
            ll1.x = __float2bfloat16(v[p].z - __bfloat162float(h2));
            ll1.y = __float2bfloat16(v[p].w - __bfloat162float(h3));
            int o = row * LDA + kv * 4;
            *(__nv_bfloat162*)(sAhi + o)     = hh0;
            *(__nv_bfloat162*)(sAhi + o + 2) = hh1;
            *(__nv_bfloat162*)(sAlo + o)     = ll0;
            *(__nv_bfloat162*)(sAlo + o + 2) = ll1;
        }
        __syncthreads();

        // ---- MMA: acc = Ah*Bh + Ah*Bl + Al*Bh ----
        wmma::fragment<wmma::accumulator, 16, 16, 16, float> acc[2][4];
        #pragma unroll
        for (int i = 0; i < 2; i++)
            #pragma unroll
            for (int j = 0; j < 4; j++)
                wmma::fill_fragment(acc[i][j], 0.0f);

        #pragma unroll
        for (int k = 0; k < 4; k++) {
            wmma::fragment<wmma::matrix_a, 16, 16, 16, __nv_bfloat16, wmma::row_major> ah[2], al[2];
            wmma::fragment<wmma::matrix_b, 16, 16, 16, __nv_bfloat16, wmma::col_major> bf[4];
            #pragma unroll
            for (int i = 0; i < 2; i++)
                wmma::load_matrix_sync(ah[i], sAhi + (wm * 32 + i * 16) * LDA + k * 16, LDA);
            #pragma unroll
            for (int j = 0; j < 4; j++)
                wmma::load_matrix_sync(bf[j], sBhi + (wn * 64 + j * 16) * LDA + k * 16, LDA);
            #pragma unroll
            for (int i = 0; i < 2; i++)
                #pragma unroll
                for (int j = 0; j < 4; j++)
                    wmma::mma_sync(acc[i][j], ah[i], bf[j], acc[i][j]);
            #pragma unroll
            for (int i = 0; i < 2; i++)
                wmma::load_matrix_sync(al[i], sAlo + (wm * 32 + i * 16) * LDA + k * 16, LDA);
            #pragma unroll
            for (int i = 0; i < 2; i++)
                #pragma unroll
                for (int j = 0; j < 4; j++)
                    wmma::mma_sync(acc[i][j], al[i], bf[j], acc[i][j]);
            #pragma unroll
            for (int j = 0; j < 4; j++)
                wmma::load_matrix_sync(bf[j], sBlo + (wn * 64 + j * 16) * LDA + k * 16, LDA);
            #pragma unroll
            for (int i = 0; i < 2; i++)
                #pragma unroll
                for (int j = 0; j < 4; j++)
                    wmma::mma_sync(acc[i][j], ah[i], bf[j], acc[i][j]);
        }
        __syncthreads();   // epilogue of previous half / conversion all done

        // ---- epilogue in two 64-column halves ----
        #pragma unroll
        for (int h = 0; h < 2; h++) {
            if (wn == h) {
                #pragma unroll
                for (int i = 0; i < 2; i++)
                    #pragma unroll
                    for (int j = 0; j < 4; j++)
                        wmma::store_matrix_sync(dbuf + (wm * 32 + i * 16) * LDH + j * 16,
                                                acc[i][j], LDH, wmma::mem_row_major);
            }
            __syncthreads();

            const int gc = h * 64 + 2 * j2;
            float cs0 = 0.f, cq0 = 0.f, cs1 = 0.f, cq1 = 0.f;
            #pragma unroll 4
            for (int r = 0; r < 16; r++) {
                int row = rg * 16 + r;
                float2 y = *(float2*)&dbuf[row * LDH + 2 * j2];
                int s = s_sidx[row], n = s_nidx[row];
                float2 p1 = __ldg((const float2*)&g_P1[(size_t)s * DOUT + gc]);
                float2 p2 = __ldg((const float2*)&g_P2[(size_t)n * DOUT + gc]);
                y.x += p1.x + p2.x;
                y.y += p1.y + p2.y;
                cs0 += y.x; cq0 += y.x * y.x;
                cs1 += y.y; cq1 += y.y * y.y;
                __half2 hy = __floats2half2_rn(y.x, y.y);
                __stcs((float*)&g_Yh[(size_t)(eb + row) * DOUT + gc],
                       __uint_as_float(*(uint32_t*)&hy));
            }
            atomicAdd(&shS[gc],     cs0);
            atomicAdd(&shQ[gc],     cq0);
            atomicAdd(&shS[gc + 1], cs1);
            atomicAdd(&shQ[gc + 1], cq1);
            __syncthreads();
        }
    }

    if (tid < 128) {
        atomicAdd(&g_colsum[tid], shS[tid]);
        atomicAdd(&g_colsq[tid],  shQ[tid]);
    }
}

__global__ void k_bn1fin(const float* __restrict__ gamma, const float* __restrict__ beta) {
    int j = threadIdx.x;
    float mean = g_colsum[j] * (1.0f / NEDGES);
    float var  = g_colsq[j] * (1.0f / NEDGES) - mean * mean;
    float aa = gamma[j] * rsqrtf(var + BN_EPS);
    g_a1[j] = aa;
    g_c1[j] = beta[j] - mean * aa;
}

// Pass 2: BN1 + gate + deterministic CSR segment sum + fused BN2 stats.
// Warp per atom: lanes 0-15 even edges, 16-31 odd; 4 columns per lane.
__global__ void __launch_bounds__(256) k_msg() {
    __shared__ float sS[ELEM], sQ[ELEM];
    const int lane = threadIdx.x;
    const int tid  = threadIdx.y * 32 + lane;
    const int a = blockIdx.x * 8 + threadIdx.y;   // grid*8 == NATOMS exactly
    if (tid < ELEM) { sS[tid] = 0.f; sQ[tid] = 0.f; }
    __syncthreads();

    const int half = lane >> 4;
    const int j4 = lane & 15;

    float a1f[4], c1f[4], a1c[4], c1c[4];
    #pragma unroll
    for (int q = 0; q < 4; q++) {
        int j = 4 * j4 + q;
        a1f[q] = g_a1[j];      c1f[q] = g_c1[j];
        a1c[q] = g_a1[64 + j]; c1c[q] = g_c1[64 + j];
    }

    const int e0 = g_rowptr[a], e1 = g_rowptr[a + 1];
    float s[4] = {0.f, 0.f, 0.f, 0.f};
    const char* Yb = (const char*)g_Yh;

    for (int e = e0 + half; e < e1; e += 2) {
        float2 fv = __ldcs((const float2*)(Yb + (size_t)e * 256 + j4 * 8));
        float2 cv = __ldcs((const float2*)(Yb + (size_t)e * 256 + 128 + j4 * 8));
        __half2 f01 = *(__half2*)&fv.x, f23 = *(__half2*)&fv.y;
        __half2 c01 = *(__half2*)&cv.x, c23 = *(__half2*)&cv.y;
        float yf, yc;
        yf = __low2float(f01)  * a1f[0] + c1f[0]; yc = __low2float(c01)  * a1c[0] + c1c[0];
        s[0] += msg_gate(yf, yc);
        yf = __high2float(f01) * a1f[1] + c1f[1]; yc = __high2float(c01) * a1c[1] + c1c[1];
        s[1] += msg_gate(yf, yc);
        yf = __low2float(f23)  * a1f[2] + c1f[2]; yc = __low2float(c23)  * a1c[2] + c1c[2];
        s[2] += msg_gate(yf, yc);
        yf = __high2float(f23) * a1f[3] + c1f[3]; yc = __high2float(c23) * a1c[3] + c1c[3];
        s[3] += msg_gate(yf, yc);
    }
    #pragma unroll
    for (int q = 0; q < 4; q++)
        s[q] += __shfl_down_sync(0xffffffff, s[q], 16);
    if (half == 0) {
        float4 st = make_float4(s[0], s[1], s[2], s[3]);
        *(float4*)&g_sumed[(size_t)a * ELEM + j4 * 4] = st;
        #pragma unroll
        for (int q = 0; q < 4; q++) {
            atomicAdd(&sS[4 * j4 + q], s[q]);
            atomicAdd(&sQ[4 * j4 + q], s[q] * s[q]);
        }
    }
    __syncthreads();
    if (tid < ELEM) {
        atomicAdd(&g_s2[tid], sS[tid]);
        atomicAdd(&g_q2[tid], sQ[tid]);
    }
}

__global__ void k_bn2fin(const float* __restrict__ gamma, const float* __restrict__ beta) {
    int j = threadIdx.x;
    float mean = g_s2[j] * (1.0f / NATOMS);
    float var  = g_q2[j] * (1.0f / NATOMS) - mean * mean;
    float aa = gamma[j] * rsqrtf(var + BN_EPS);
    g_a2[j] = aa;
    g_c2[j] = beta[j] - mean * aa;
}

__global__ void k_final(const float* __restrict__ atom, float* __restrict__ out) {
    int i = blockIdx.x * blockDim.x + threadIdx.x;
    if (i >= NATOMS * ELEM) return;
    int j = i & 63;
    float v = atom[i] + g_sumed[i] * g_a2[j] + g_c2[j];
    out[i] = softplusf(v);
}

// ---------------- launch ----------------
extern "C" void kernel_launch(void* const* d_in, const int* in_sizes, int n_in,
                              void* d_out, int out_size) {
    const float* atom = (const float*)d_in[0];
    const float* nbr  = (const float*)d_in[1];
    const int*   sidx = (const int*)d_in[2];
    const int*   nidx = (const int*)d_in[3];
    const float* W    = (const float*)d_in[4];
    const float* bias = (const float*)d_in[5];
    const float* g1   = (const float*)d_in[6];
    const float* be1  = (const float*)d_in[7];
    const float* g2   = (const float*)d_in[8];
    const float* be2  = (const float*)d_in[9];
    float* out = (float*)d_out;

    cudaFuncSetAttribute(k_y_mma, cudaFuncAttributeMaxDynamicSharedMemorySize, SM_TOTAL);
    cudaFuncSetAttribute(k_precompute, cudaFuncAttributeMaxDynamicSharedMemorySize, PRE_SMEM);

    k_init<<<1, 128>>>();
    k_precompute<<<(NATOMS + 127) / 128, 256, PRE_SMEM>>>(atom, W, bias);
    k_rowptr<<<(NATOMS + 1 + 255) / 256, 256>>>(sidx);
    k_y_mma<<<GRID_Y, 256, SM_TOTAL>>>(nbr, sidx, nidx, W);
    k_bn1fin<<<1, DOUT>>>(g1, be1);
    dim3 mblk(32, 8);
    k_msg<<<NATOMS / 8, mblk>>>();
    k_bn2fin<<<1, ELEM>>>(g2, be2);
    k_final<<<(NATOMS * ELEM + 255) / 256, 256>>>(atom, out);
}

// round 6
// speedup vs baseline: 3.5995x; 1.0634x over previous
#include <cuda_runtime.h>
#include <cuda_bf16.h>
#include <cuda_fp16.h>
#include <math.h>
#include <stdint.h>

#define NATOMS 50000
#define NEDGES 800000
#define ELEM   64
#define DOUT   128
#define BN_EPS 1e-5f
#define NTILES (NEDGES / 128)     // 6250
#define GRID_Y 296                // persistent, 2 CTAs/SM

// ---------------- scratch (device globals; no allocation allowed) ----------------
__device__ float  g_P1[(size_t)NATOMS * DOUT];   // atom @ W1 + b
__device__ float  g_P2[(size_t)NATOMS * DOUT];   // atom @ W2
__device__ __half g_Yh[(size_t)NEDGES * DOUT];   // pre-BN edge features, fp16
__device__ int    g_rowptr[NATOMS + 1];
__device__ float  g_colsum[DOUT];
__device__ float  g_colsq [DOUT];
__device__ float  g_a1[DOUT], g_c1[DOUT];
__device__ float  g_sumed[(size_t)NATOMS * ELEM];
__device__ float  g_s2[ELEM], g_q2[ELEM];
__device__ float  g_a2[ELEM], g_c2[ELEM];

// ---------------- helpers ----------------
__device__ __forceinline__ float softplusf(float x) {
    return log1pf(expf(-fabsf(x))) + fmaxf(x, 0.0f);
}
__device__ __forceinline__ float msg_gate(float yf, float yc) {
    float ef  = __expf(-yf);
    float sig = __fdividef(1.0f, 1.0f + ef);
    float ec  = __expf(-fabsf(yc));
    float sp  = __logf(1.0f + ec) + fmaxf(yc, 0.0f);
    return sig * sp;
}
__device__ __forceinline__ void fma4(float4& a, float x, const float4 w) {
    a.x += x * w.x; a.y += x * w.y; a.z += x * w.z; a.w += x * w.w;
}
__device__ __forceinline__ float4 add4(float4 a, float4 b) {
    return make_float4(a.x + b.x, a.y + b.y, a.z + b.z, a.w + b.w);
}
// raw bf16 mma m16n8k16, fp32 accum (documented fragment layout)
__device__ __forceinline__ void mma_bf16(float4& d, uint32_t a0, uint32_t a1,
                                         uint32_t a2, uint32_t a3,
                                         uint32_t b0, uint32_t b1) {
    asm volatile(
        "mma.sync.aligned.m16n8k16.row.col.f32.bf16.bf16.f32 "
        "{%0,%1,%2,%3}, {%4,%5,%6,%7}, {%8,%9}, {%0,%1,%2,%3};"
        : "+f"(d.x), "+f"(d.y), "+f"(d.z), "+f"(d.w)
        : "r"(a0), "r"(a1), "r"(a2), "r"(a3), "r"(b0), "r"(b1));
}
__device__ __forceinline__ uint32_t bf2_bits(__nv_bfloat162 h) {
    return *reinterpret_cast<uint32_t*>(&h);
}

// ---------------- SMEM layout for k_y (bytes) ----------------
#define LDA 72            // fp32 A leading dim (8-bank row shift -> conflict-free lds.64)
#define LDB 72            // bf16 B leading dim (4-bank row shift -> conflict-free lds.32)
#define SM_SIDX 0         // 128 ints
#define SM_NIDX 512
#define SM_A    1024      // 128 x LDA fp32 = 36864
#define SM_BH   37888     // B^T hi: [n=128][k=64] bf16, 18432
#define SM_BL   56320     // B^T lo
#define SM_TOTAL 74752    // 73 KB -> 2 CTAs/SM

// ---------------- kernels ----------------
__global__ void k_init() {
    int t = threadIdx.x;
    if (t < DOUT) { g_colsum[t] = 0.f; g_colsq[t] = 0.f; }
    if (t < ELEM) { g_s2[t] = 0.f; g_q2[t] = 0.f; }
}

__global__ void k_rowptr(const int* __restrict__ sidx) {
    int a = blockIdx.x * blockDim.x + threadIdx.x;
    if (a > NATOMS) return;
    int lo = 0, hi = NEDGES;
    while (lo < hi) {
        int mid = (lo + hi) >> 1;
        if (sidx[mid] < a) lo = mid + 1; else hi = mid;
    }
    g_rowptr[a] = lo;
}

// P1 = atom @ W[0:64] + b ;  P2 = atom @ W[64:128].  128 atoms per block.
#define PRE_LDAT 68
#define PRE_SW   (64 * DOUT)
#define PRE_SMEM ((PRE_SW + 128 * PRE_LDAT) * 4)
__global__ void __launch_bounds__(256) k_precompute(const float* __restrict__ atom,
                                                    const float* __restrict__ W,
                                                    const float* __restrict__ bias) {
    extern __shared__ float psm[];
    float* sW  = psm;
    float* sAt = psm + PRE_SW;
    const int tid = threadIdx.x;
    const int ab = blockIdx.x * 128;
    const int nvalid = min(128, NATOMS - ab);

    #pragma unroll
    for (int p = 0; p < 8; p++) {
        int i4 = tid + p * 256;
        int a = i4 >> 4, kv = i4 & 15;
        float4 v = make_float4(0.f, 0.f, 0.f, 0.f);
        if (a < nvalid) v = *(const float4*)(atom + (size_t)(ab + a) * ELEM + kv * 4);
        *(float4*)&sAt[a * PRE_LDAT + kv * 4] = v;
    }

    const int a  = tid >> 1;
    const int ob = (tid & 1) * 64;

    for (int phase = 0; phase < 2; phase++) {
        __syncthreads();
        #pragma unroll
        for (int p = 0; p < 8; p++) {
            int i4 = tid + p * 256;
            int k = i4 >> 5, j4 = i4 & 31;
            *(float4*)&sW[k * DOUT + j4 * 4] =
                *(const float4*)(W + (size_t)(phase * 64 + k) * DOUT + j4 * 4);
        }
        __syncthreads();

        float4 acc[16];
        #pragma unroll
        for (int q = 0; q < 16; q++) acc[q] = make_float4(0.f, 0.f, 0.f, 0.f);
        #pragma unroll 4
        for (int k = 0; k < 64; k++) {
            float x = sAt[a * PRE_LDAT + k];
            #pragma unroll
            for (int q = 0; q < 16; q++) fma4(acc[q], x, *(float4*)&sW[k * DOUT + ob + q * 4]);
        }
        if (a < nvalid) {
            float* dst = (phase == 0 ? g_P1 : g_P2) + (size_t)(ab + a) * DOUT + ob;
            #pragma unroll
            for (int q = 0; q < 16; q++) {
                float4 v = acc[q];
                if (phase == 0) v = add4(v, *(const float4*)(bias + ob + q * 4));
                *(float4*)(dst + q * 4) = v;
            }
        }
    }
}

// Pass 1 (raw HMMA, no dbuf): per 128-edge tile, G = nbr @ W3 via bf16 hi/lo
// split (Ah*Bh + Ah*Bl + Al*Bh); epilogue directly from accumulator registers.
__global__ void __launch_bounds__(256, 2) k_y_mma(const float* __restrict__ nbr,
                                                  const int* __restrict__ sidx,
                                                  const int* __restrict__ nidx,
                                                  const float* __restrict__ W) {
    extern __shared__ char sm[];
    int*   s_sidx = (int*)(sm + SM_SIDX);
    int*   s_nidx = (int*)(sm + SM_NIDX);
    float* sA     = (float*)(sm + SM_A);
    __nv_bfloat16* sBh = (__nv_bfloat16*)(sm + SM_BH);
    __nv_bfloat16* sBl = (__nv_bfloat16*)(sm + SM_BL);

    const int tid  = threadIdx.x;
    const int wid  = tid >> 5;
    const int lane = tid & 31;
    const int wm   = wid >> 1;          // warp row block (32 rows)
    const int wn   = wid & 1;           // warp col block (64 cols)
    const int g    = lane >> 2;         // groupID
    const int tg   = lane & 3;          // thread-in-group

    // Stage B^T hi/lo: B[n][k] = W[(128+k)*128 + n]
    for (int p = 0; p < 32; p++) {
        int idx = p * 256 + tid;
        int k = idx >> 7, n = idx & 127;
        float v = W[(size_t)(128 + k) * DOUT + n];
        __nv_bfloat16 h = __float2bfloat16(v);
        sBh[n * LDB + k] = h;
        sBl[n * LDB + k] = __float2bfloat16(v - __bfloat162float(h));
    }
    __syncthreads();

    // persistent BN1 stats in registers: 16 columns owned by this thread
    float cs[16], cq[16];
    #pragma unroll
    for (int q = 0; q < 16; q++) { cs[q] = 0.f; cq[q] = 0.f; }

    for (int t = blockIdx.x; t < NTILES; t += GRID_Y) {
        const int eb = t * 128;

        // ---- stage A tile fp32 (streaming reads) ----
        float4 v[8];
        #pragma unroll
        for (int p = 0; p < 8; p++)
            v[p] = __ldcs((const float4*)(nbr + (size_t)eb * ELEM) + tid + p * 256);
        if (tid < 128) {
            s_sidx[tid] = __ldg(sidx + eb + tid);
            s_nidx[tid] = __ldg(nidx + eb + tid);
        }
        #pragma unroll
        for (int p = 0; p < 8; p++) {
            int i4 = tid + p * 256;
            int row = i4 >> 4, kv = i4 & 15;
            *(float4*)&sA[row * LDA + kv * 4] = v[p];
        }
        __syncthreads();

        // ---- MMA: acc = Ah*Bh + Ah*Bl + Al*Bh ----
        float4 acc[2][8];
        #pragma unroll
        for (int i = 0; i < 2; i++)
            #pragma unroll
            for (int j = 0; j < 8; j++)
                acc[i][j] = make_float4(0.f, 0.f, 0.f, 0.f);

        #pragma unroll
        for (int ks = 0; ks < 4; ks++) {
            const int c0 = ks * 16 + tg * 2;
            // build A fragments hi/lo in registers (fp32 SMEM -> bf16x2)
            uint32_t ah[2][4], al[2][4];
            #pragma unroll
            for (int i = 0; i < 2; i++) {
                const float* rlo = sA + (wm * 32 + i * 16 + g) * LDA;
                const float* rhi = rlo + 8 * LDA;
                float2 w0 = *(const float2*)(rlo + c0);
                float2 w1 = *(const float2*)(rhi + c0);
                float2 w2 = *(const float2*)(rlo + c0 + 8);
                float2 w3 = *(const float2*)(rhi + c0 + 8);
                __nv_bfloat162 h0 = __float22bfloat162_rn(w0);
                __nv_bfloat162 h1 = __float22bfloat162_rn(w1);
                __nv_bfloat162 h2 = __float22bfloat162_rn(w2);
                __nv_bfloat162 h3 = __float22bfloat162_rn(w3);
                ah[i][0] = bf2_bits(h0); ah[i][1] = bf2_bits(h1);
                ah[i][2] = bf2_bits(h2); ah[i][3] = bf2_bits(h3);
                al[i][0] = bf2_bits(__float22bfloat162_rn(make_float2(
                    w0.x - __bfloat162float(__low2bfloat16(h0)), w0.y - __bfloat162float(__high2bfloat16(h0)))));
                al[i][1] = bf2_bits(__float22bfloat162_rn(make_float2(
                    w1.x - __bfloat162float(__low2bfloat16(h1)), w1.y - __bfloat162float(__high2bfloat16(h1)))));
                al[i][2] = bf2_bits(__float22bfloat162_rn(make_float2(
                    w2.x - __bfloat162float(__low2bfloat16(h2)), w2.y - __bfloat162float(__high2bfloat16(h2)))));
                al[i][3] = bf2_bits(__float22bfloat162_rn(make_float2(
                    w3.x - __bfloat162float(__low2bfloat16(h3)), w3.y - __bfloat162float(__high2bfloat16(h3)))));
            }
            #pragma unroll
            for (int j = 0; j < 8; j++) {
                const int n = wn * 64 + j * 8 + g;
                const __nv_bfloat16* bph = sBh + n * LDB + c0;
                const __nv_bfloat16* bpl = sBl + n * LDB + c0;
                uint32_t bh0 = *(const uint32_t*)bph;
                uint32_t bh1 = *(const uint32_t*)(bph + 8);
                uint32_t bl0 = *(const uint32_t*)bpl;
                uint32_t bl1 = *(const uint32_t*)(bpl + 8);
                #pragma unroll
                for (int i = 0; i < 2; i++) {
                    mma_bf16(acc[i][j], ah[i][0], ah[i][1], ah[i][2], ah[i][3], bh0, bh1);
                    mma_bf16(acc[i][j], ah[i][0], ah[i][1], ah[i][2], ah[i][3], bl0, bl1);
                    mma_bf16(acc[i][j], al[i][0], al[i][1], al[i][2], al[i][3], bh0, bh1);
                }
            }
        }

        // ---- epilogue straight from registers ----
        #pragma unroll
        for (int i = 0; i < 2; i++) {
            #pragma unroll
            for (int rr = 0; rr < 2; rr++) {
                const int row = wm * 32 + i * 16 + rr * 8 + g;
                const int s = s_sidx[row], n = s_nidx[row];
                const float*  p1r = g_P1 + (size_t)s * DOUT + wn * 64 + tg * 2;
                const float*  p2r = g_P2 + (size_t)n * DOUT + wn * 64 + tg * 2;
                __half* yr = g_Yh + (size_t)(eb + row) * DOUT + wn * 64 + tg * 2;
                #pragma unroll
                for (int j = 0; j < 8; j++) {
                    float2 p1 = __ldg((const float2*)(p1r + j * 8));
                    float2 p2 = __ldg((const float2*)(p2r + j * 8));
                    float y0 = (rr ? acc[i][j].z : acc[i][j].x) + p1.x + p2.x;
                    float y1 = (rr ? acc[i][j].w : acc[i][j].y) + p1.y + p2.y;
                    cs[2 * j]     += y0; cq[2 * j]     += y0 * y0;
                    cs[2 * j + 1] += y1; cq[2 * j + 1] += y1 * y1;
                    __half2 hy = __floats2half2_rn(y0, y1);
                    __stcs((float*)(yr + j * 8), __uint_as_float(*(uint32_t*)&hy));
                }
            }
        }
        __syncthreads();   // epilogue used s_sidx; next staging overwrites sA/idx
    }

    // ---- BN1 stats: reduce across lanes with same tg, then global atomics ----
    #pragma unroll
    for (int q = 0; q < 16; q++) {
        cs[q] += __shfl_xor_sync(0xffffffff, cs[q], 4);
        cs[q] += __shfl_xor_sync(0xffffffff, cs[q], 8);
        cs[q] += __shfl_xor_sync(0xffffffff, cs[q], 16);
        cq[q] += __shfl_xor_sync(0xffffffff, cq[q], 4);
        cq[q] += __shfl_xor_sync(0xffffffff, cq[q], 8);
        cq[q] += __shfl_xor_sync(0xffffffff, cq[q], 16);
    }
    if (g == 0) {
        #pragma unroll
        for (int j = 0; j < 8; j++) {
            #pragma unroll
            for (int b = 0; b < 2; b++) {
                int col = wn * 64 + j * 8 + tg * 2 + b;
                atomicAdd(&g_colsum[col], cs[2 * j + b]);
                atomicAdd(&g_colsq[col],  cq[2 * j + b]);
            }
        }
    }
}

__global__ void k_bn1fin(const float* __restrict__ gamma, const float* __restrict__ beta) {
    int j = threadIdx.x;
    float mean = g_colsum[j] * (1.0f / NEDGES);
    float var  = g_colsq[j] * (1.0f / NEDGES) - mean * mean;
    float aa = gamma[j] * rsqrtf(var + BN_EPS);
    g_a1[j] = aa;
    g_c1[j] = beta[j] - mean * aa;
}

// Pass 2: BN1 + gate + deterministic CSR segment sum + fused BN2 stats.
// Warp per atom, 4 edges in flight: quarter = lane>>3, 8 cols per lane.
__global__ void __launch_bounds__(256) k_msg() {
    __shared__ float sS[ELEM], sQ[ELEM];
    const int lane = threadIdx.x;
    const int tid  = threadIdx.y * 32 + lane;
    const int a = blockIdx.x * 8 + threadIdx.y;   // grid*8 == NATOMS
    if (tid < ELEM) { sS[tid] = 0.f; sQ[tid] = 0.f; }
    __syncthreads();

    const int quarter = lane >> 3;
    const int j8 = lane & 7;              // cols 8*j8 .. 8*j8+7

    float a1f[8], c1f[8], a1c[8], c1c[8];
    #pragma unroll
    for (int q = 0; q < 8; q++) {
        int j = 8 * j8 + q;
        a1f[q] = g_a1[j];      c1f[q] = g_c1[j];
        a1c[q] = g_a1[64 + j]; c1c[q] = g_c1[64 + j];
    }

    const int e0 = g_rowptr[a], e1 = g_rowptr[a + 1];
    float s[8];
    #pragma unroll
    for (int q = 0; q < 8; q++) s[q] = 0.f;
    const char* Yb = (const char*)g_Yh;

    for (int e = e0 + quarter; e < e1; e += 4) {
        float4 fv = __ldcs((const float4*)(Yb + (size_t)e * 256 + j8 * 16));
        float4 cv = __ldcs((const float4*)(Yb + (size_t)e * 256 + 128 + j8 * 16));
        const __half2* f2 = (const __half2*)&fv;
        const __half2* c2 = (const __half2*)&cv;
        #pragma unroll
        for (int p = 0; p < 4; p++) {
            float yf0 = __low2float(f2[p])  * a1f[2*p]   + c1f[2*p];
            float yc0 = __low2float(c2[p])  * a1c[2*p]   + c1c[2*p];
            s[2*p]   += msg_gate(yf0, yc0);
            float yf1 = __high2float(f2[p]) * a1f[2*p+1] + c1f[2*p+1];
            float yc1 = __high2float(c2[p]) * a1c[2*p+1] + c1c[2*p+1];
            s[2*p+1] += msg_gate(yf1, yc1);
        }
    }
    #pragma unroll
    for (int q = 0; q < 8; q++) {
        s[q] += __shfl_xor_sync(0xffffffff, s[q], 8);
        s[q] += __shfl_xor_sync(0xffffffff, s[q], 16);
    }
    if (quarter == 0) {
        float4 st0 = make_float4(s[0], s[1], s[2], s[3]);
        float4 st1 = make_float4(s[4], s[5], s[6], s[7]);
        *(float4*)&g_sumed[(size_t)a * ELEM + j8 * 8]     = st0;
        *(float4*)&g_sumed[(size_t)a * ELEM + j8 * 8 + 4] = st1;
        #pragma unroll
        for (int q = 0; q < 8; q++) {
            atomicAdd(&sS[8 * j8 + q], s[q]);
            atomicAdd(&sQ[8 * j8 + q], s[q] * s[q]);
        }
    }
    __syncthreads();
    if (tid < ELEM) {
        atomicAdd(&g_s2[tid], sS[tid]);
        atomicAdd(&g_q2[tid], sQ[tid]);
    }
}

__global__ void k_bn2fin(const float* __restrict__ gamma, const float* __restrict__ beta) {
    int j = threadIdx.x;
    float mean = g_s2[j] * (1.0f / NATOMS);
    float var  = g_q2[j] * (1.0f / NATOMS) - mean * mean;
    float aa = gamma[j] * rsqrtf(var + BN_EPS);
    g_a2[j] = aa;
    g_c2[j] = beta[j] - mean * aa;
}

__global__ void k_final(const float* __restrict__ atom, float* __restrict__ out) {
    int i4 = blockIdx.x * blockDim.x + threadIdx.x;
    if (i4 >= NATOMS * ELEM / 4) return;
    int base = i4 * 4;
    int j = base & 63;
    float4 av = *(const float4*)(atom + base);
    float4 sv = *(const float4*)(g_sumed + base);
    float4 o;
    o.x = softplusf(av.x + sv.x * g_a2[j]     + g_c2[j]);
    o.y = softplusf(av.y + sv.y * g_a2[j + 1] + g_c2[j + 1]);
    o.z = softplusf(av.z + sv.z * g_a2[j + 2] + g_c2[j + 2]);
    o.w = softplusf(av.w + sv.w * g_a2[j + 3] + g_c2[j + 3]);
    *(float4*)(out + base) = o;
}

// ---------------- launch ----------------
extern "C" void kernel_launch(void* const* d_in, const int* in_sizes, int n_in,
                              void* d_out, int out_size) {
    const float* atom = (const float*)d_in[0];
    const float* nbr  = (const float*)d_in[1];
    const int*   sidx = (const int*)d_in[2];
    const int*   nidx = (const int*)d_in[3];
    const float* W    = (const float*)d_in[4];
    const float* bias = (const float*)d_in[5];
    const float* g1   = (const float*)d_in[6];
    const float* be1  = (const float*)d_in[7];
    const float* g2   = (const float*)d_in[8];
    const float* be2  = (const float*)d_in[9];
    float* out = (float*)d_out;

    cudaFuncSetAttribute(k_y_mma, cudaFuncAttributeMaxDynamicSharedMemorySize, SM_TOTAL);
    cudaFuncSetAttribute(k_precompute, cudaFuncAttributeMaxDynamicSharedMemorySize, PRE_SMEM);

    k_init<<<1, 128>>>();
    k_precompute<<<(NATOMS + 127) / 128, 256, PRE_SMEM>>>(atom, W, bias);
    k_rowptr<<<(NATOMS + 1 + 255) / 256, 256>>>(sidx);
    k_y_mma<<<GRID_Y, 256, SM_TOTAL>>>(nbr, sidx, nidx, W);
    k_bn1fin<<<1, DOUT>>>(g1, be1);
    dim3 mblk(32, 8);
    k_msg<<<NATOMS / 8, mblk>>>();
    k_bn2fin<<<1, ELEM>>>(g2, be2);
    k_final<<<(NATOMS * ELEM / 4 + 255) / 256, 256>>>(atom, out);
}

// round 7
// speedup vs baseline: 3.6077x; 1.0023x over previous
#include <cuda_runtime.h>
#include <cuda_bf16.h>
#include <cuda_fp16.h>
#include <math.h>
#include <stdint.h>

#define NATOMS 50000
#define NEDGES 800000
#define ELEM   64
#define DOUT   128
#define BN_EPS 1e-5f
#define NTILES (NEDGES / 128)     // 6250
#define GRID_Y 296                // persistent, 2 CTAs/SM

// ---------------- scratch (device globals; no allocation allowed) ----------------
__device__ float  g_P1[(size_t)NATOMS * DOUT];   // atom @ W1 + b
__device__ float  g_P2[(size_t)NATOMS * DOUT];   // atom @ W2
__device__ __half g_Yh[(size_t)NEDGES * DOUT];   // pre-BN edge features, fp16
__device__ int    g_rowptr[NATOMS + 1];
__device__ float  g_colsum[DOUT];
__device__ float  g_colsq [DOUT];
__device__ float  g_a1[DOUT], g_c1[DOUT];
__device__ float  g_sumed[(size_t)NATOMS * ELEM];
__device__ float  g_s2[ELEM], g_q2[ELEM];
__device__ float  g_a2[ELEM], g_c2[ELEM];

// ---------------- helpers ----------------
__device__ __forceinline__ float softplusf(float x) {
    return log1pf(expf(-fabsf(x))) + fmaxf(x, 0.0f);
}
__device__ __forceinline__ float msg_gate(float yf, float yc) {
    float ef  = __expf(-yf);
    float sig = __fdividef(1.0f, 1.0f + ef);
    float ec  = __expf(-fabsf(yc));
    float sp  = __logf(1.0f + ec) + fmaxf(yc, 0.0f);
    return sig * sp;
}
__device__ __forceinline__ void fma4(float4& a, float x, const float4 w) {
    a.x += x * w.x; a.y += x * w.y; a.z += x * w.z; a.w += x * w.w;
}
__device__ __forceinline__ float4 add4(float4 a, float4 b) {
    return make_float4(a.x + b.x, a.y + b.y, a.z + b.z, a.w + b.w);
}
__device__ __forceinline__ void mma_bf16(float4& d, uint32_t a0, uint32_t a1,
                                         uint32_t a2, uint32_t a3,
                                         uint32_t b0, uint32_t b1) {
    asm volatile(
        "mma.sync.aligned.m16n8k16.row.col.f32.bf16.bf16.f32 "
        "{%0,%1,%2,%3}, {%4,%5,%6,%7}, {%8,%9}, {%0,%1,%2,%3};"
        : "+f"(d.x), "+f"(d.y), "+f"(d.z), "+f"(d.w)
        : "r"(a0), "r"(a1), "r"(a2), "r"(a3), "r"(b0), "r"(b1));
}
__device__ __forceinline__ uint32_t bf2_bits(__nv_bfloat162 h) {
    return *reinterpret_cast<uint32_t*>(&h);
}
__device__ __forceinline__ uint32_t h2_bits(__half2 h) {
    return *reinterpret_cast<uint32_t*>(&h);
}

// ---------------- SMEM layout for k_y (bytes) ----------------
#define LDA 72
#define LDB 72
#define SM_SIDX 0
#define SM_NIDX 512
#define SM_A    1024      // 128 x LDA fp32 = 36864
#define SM_BH   37888     // B^T hi (col-permuted): [n=128][k=64] bf16
#define SM_BL   56320
#define SM_TOTAL 74752    // 73 KB -> 2 CTAs/SM

// ---------------- kernels ----------------
__global__ void k_init() {
    int t = threadIdx.x;
    if (t < DOUT) { g_colsum[t] = 0.f; g_colsq[t] = 0.f; }
    if (t < ELEM) { g_s2[t] = 0.f; g_q2[t] = 0.f; }
}

__global__ void k_rowptr(const int* __restrict__ sidx) {
    int a = blockIdx.x * blockDim.x + threadIdx.x;
    if (a > NATOMS) return;
    int lo = 0, hi = NEDGES;
    while (lo < hi) {
        int mid = (lo + hi) >> 1;
        if (sidx[mid] < a) lo = mid + 1; else hi = mid;
    }
    g_rowptr[a] = lo;
}

// P1 = atom @ W[0:64] + b ;  P2 = atom @ W[64:128].  128 atoms per block.
#define PRE_LDAT 68
#define PRE_SW   (64 * DOUT)
#define PRE_SMEM ((PRE_SW + 128 * PRE_LDAT) * 4)
__global__ void __launch_bounds__(256) k_precompute(const float* __restrict__ atom,
                                                    const float* __restrict__ W,
                                                    const float* __restrict__ bias) {
    extern __shared__ float psm[];
    float* sW  = psm;
    float* sAt = psm + PRE_SW;
    const int tid = threadIdx.x;
    const int ab = blockIdx.x * 128;
    const int nvalid = min(128, NATOMS - ab);

    #pragma unroll
    for (int p = 0; p < 8; p++) {
        int i4 = tid + p * 256;
        int a = i4 >> 4, kv = i4 & 15;
        float4 v = make_float4(0.f, 0.f, 0.f, 0.f);
        if (a < nvalid) v = *(const float4*)(atom + (size_t)(ab + a) * ELEM + kv * 4);
        *(float4*)&sAt[a * PRE_LDAT + kv * 4] = v;
    }

    const int a  = tid >> 1;
    const int ob = (tid & 1) * 64;

    for (int phase = 0; phase < 2; phase++) {
        __syncthreads();
        #pragma unroll
        for (int p = 0; p < 8; p++) {
            int i4 = tid + p * 256;
            int k = i4 >> 5, j4 = i4 & 31;
            *(float4*)&sW[k * DOUT + j4 * 4] =
                *(const float4*)(W + (size_t)(phase * 64 + k) * DOUT + j4 * 4);
        }
        __syncthreads();

        float4 acc[16];
        #pragma unroll
        for (int q = 0; q < 16; q++) acc[q] = make_float4(0.f, 0.f, 0.f, 0.f);
        #pragma unroll 4
        for (int k = 0; k < 64; k++) {
            float x = sAt[a * PRE_LDAT + k];
            #pragma unroll
            for (int q = 0; q < 16; q++) fma4(acc[q], x, *(float4*)&sW[k * DOUT + ob + q * 4]);
        }
        if (a < nvalid) {
            float* dst = (phase == 0 ? g_P1 : g_P2) + (size_t)(ab + a) * DOUT + ob;
            #pragma unroll
            for (int q = 0; q < 16; q++) {
                float4 v = acc[q];
                if (phase == 0) v = add4(v, *(const float4*)(bias + ob + q * 4));
                *(float4*)(dst + q * 4) = v;
            }
        }
    }
}

// Pass 1 (raw HMMA, column-permuted B): per 128-edge tile, G = nbr @ W3 via
// bf16 hi/lo split; epilogue from registers with CONTIGUOUS 16-col/thread
// global accesses (the B permutation maps acc col j*8+tg*2+b -> logical
// tg*16+j*2+b, so Y / P1 / P2 are accessed as float4/uint4).
__global__ void __launch_bounds__(256, 2) k_y_mma(const float* __restrict__ nbr,
                                                  const int* __restrict__ sidx,
                                                  const int* __restrict__ nidx,
                                                  const float* __restrict__ W) {
    extern __shared__ char sm[];
    int*   s_sidx = (int*)(sm + SM_SIDX);
    int*   s_nidx = (int*)(sm + SM_NIDX);
    float* sA     = (float*)(sm + SM_A);
    __nv_bfloat16* sBh = (__nv_bfloat16*)(sm + SM_BH);
    __nv_bfloat16* sBl = (__nv_bfloat16*)(sm + SM_BL);

    const int tid  = threadIdx.x;
    const int wid  = tid >> 5;
    const int lane = tid & 31;
    const int wm   = wid >> 1;
    const int wn   = wid & 1;
    const int g    = lane >> 2;
    const int tg   = lane & 3;

    // Stage B^T hi/lo with column permutation:
    // physical slot n (0..127): half h=n>>6, pp=n&63; logical within-half
    // l = ((pp>>1)&3)*16 + (pp>>3)*2 + (pp&1); source W column = h*64 + l.
    for (int p = 0; p < 32; p++) {
        int idx = p * 256 + tid;
        int k = idx >> 7, n = idx & 127;
        int h = n >> 6, pp = n & 63;
        int l = ((pp >> 1) & 3) * 16 + (pp >> 3) * 2 + (pp & 1);
        float v = W[(size_t)(128 + k) * DOUT + h * 64 + l];
        __nv_bfloat16 hb = __float2bfloat16(v);
        sBh[n * LDB + k] = hb;
        sBl[n * LDB + k] = __float2bfloat16(v - __bfloat162float(hb));
    }
    __syncthreads();

    // persistent BN1 stats: 16 logical columns owned by this thread
    float cs[16], cq[16];
    #pragma unroll
    for (int q = 0; q < 16; q++) { cs[q] = 0.f; cq[q] = 0.f; }
    const int colbase = wn * 64 + tg * 16;

    for (int t = blockIdx.x; t < NTILES; t += GRID_Y) {
        const int eb = t * 128;

        // ---- stage A tile fp32 (streaming reads) ----
        float4 v[8];
        #pragma unroll
        for (int p = 0; p < 8; p++)
            v[p] = __ldcs((const float4*)(nbr + (size_t)eb * ELEM) + tid + p * 256);
        if (tid < 128) {
            s_sidx[tid] = __ldg(sidx + eb + tid);
            s_nidx[tid] = __ldg(nidx + eb + tid);
        }
        #pragma unroll
        for (int p = 0; p < 8; p++) {
            int i4 = tid + p * 256;
            int row = i4 >> 4, kv = i4 & 15;
            *(float4*)&sA[row * LDA + kv * 4] = v[p];
        }
        __syncthreads();

        // ---- MMA: acc = Ah*Bh + Ah*Bl + Al*Bh ----
        float4 acc[2][8];
        #pragma unroll
        for (int i = 0; i < 2; i++)
            #pragma unroll
            for (int j = 0; j < 8; j++)
                acc[i][j] = make_float4(0.f, 0.f, 0.f, 0.f);

        #pragma unroll
        for (int ks = 0; ks < 4; ks++) {
            const int c0 = ks * 16 + tg * 2;
            uint32_t ah[2][4], al[2][4];
            #pragma unroll
            for (int i = 0; i < 2; i++) {
                const float* rlo = sA + (wm * 32 + i * 16 + g) * LDA;
                const float* rhi = rlo + 8 * LDA;
                float2 w0 = *(const float2*)(rlo + c0);
                float2 w1 = *(const float2*)(rhi + c0);
                float2 w2 = *(const float2*)(rlo + c0 + 8);
                float2 w3 = *(const float2*)(rhi + c0 + 8);
                __nv_bfloat162 h0 = __float22bfloat162_rn(w0);
                __nv_bfloat162 h1 = __float22bfloat162_rn(w1);
                __nv_bfloat162 h2 = __float22bfloat162_rn(w2);
                __nv_bfloat162 h3 = __float22bfloat162_rn(w3);
                ah[i][0] = bf2_bits(h0); ah[i][1] = bf2_bits(h1);
                ah[i][2] = bf2_bits(h2); ah[i][3] = bf2_bits(h3);
                al[i][0] = bf2_bits(__float22bfloat162_rn(make_float2(
                    w0.x - __bfloat162float(__low2bfloat16(h0)), w0.y - __bfloat162float(__high2bfloat16(h0)))));
                al[i][1] = bf2_bits(__float22bfloat162_rn(make_float2(
                    w1.x - __bfloat162float(__low2bfloat16(h1)), w1.y - __bfloat162float(__high2bfloat16(h1)))));
                al[i][2] = bf2_bits(__float22bfloat162_rn(make_float2(
                    w2.x - __bfloat162float(__low2bfloat16(h2)), w2.y - __bfloat162float(__high2bfloat16(h2)))));
                al[i][3] = bf2_bits(__float22bfloat162_rn(make_float2(
                    w3.x - __bfloat162float(__low2bfloat16(h3)), w3.y - __bfloat162float(__high2bfloat16(h3)))));
            }
            #pragma unroll
            for (int j = 0; j < 8; j++) {
                const int n = wn * 64 + j * 8 + g;
                const __nv_bfloat16* bph = sBh + n * LDB + c0;
                const __nv_bfloat16* bpl = sBl + n * LDB + c0;
                uint32_t bh0 = *(const uint32_t*)bph;
                uint32_t bh1 = *(const uint32_t*)(bph + 8);
                uint32_t bl0 = *(const uint32_t*)bpl;
                uint32_t bl1 = *(const uint32_t*)(bpl + 8);
                #pragma unroll
                for (int i = 0; i < 2; i++) {
                    mma_bf16(acc[i][j], ah[i][0], ah[i][1], ah[i][2], ah[i][3], bh0, bh1);
                    mma_bf16(acc[i][j], ah[i][0], ah[i][1], ah[i][2], ah[i][3], bl0, bl1);
                    mma_bf16(acc[i][j], al[i][0], al[i][1], al[i][2], al[i][3], bh0, bh1);
                }
            }
        }

        // ---- epilogue: contiguous 16 logical cols per thread ----
        #pragma unroll
        for (int i = 0; i < 2; i++) {
            #pragma unroll
            for (int rr = 0; rr < 2; rr++) {
                const int row = wm * 32 + i * 16 + rr * 8 + g;
                const int s = s_sidx[row], n = s_nidx[row];
                const float* p1r = g_P1 + (size_t)s * DOUT + colbase;
                const float* p2r = g_P2 + (size_t)n * DOUT + colbase;
                uint32_t hb[8];
                #pragma unroll
                for (int qq = 0; qq < 4; qq++) {
                    float4 p1 = __ldg((const float4*)(p1r + qq * 4));
                    float4 p2 = __ldg((const float4*)(p2r + qq * 4));
                    const int j0 = qq * 2, j1 = qq * 2 + 1;
                    float y0 = (rr ? acc[i][j0].z : acc[i][j0].x) + p1.x + p2.x;
                    float y1 = (rr ? acc[i][j0].w : acc[i][j0].y) + p1.y + p2.y;
                    float y2 = (rr ? acc[i][j1].z : acc[i][j1].x) + p1.z + p2.z;
                    float y3 = (rr ? acc[i][j1].w : acc[i][j1].y) + p1.w + p2.w;
                    cs[qq*4+0] += y0; cq[qq*4+0] += y0 * y0;
                    cs[qq*4+1] += y1; cq[qq*4+1] += y1 * y1;
                    cs[qq*4+2] += y2; cq[qq*4+2] += y2 * y2;
                    cs[qq*4+3] += y3; cq[qq*4+3] += y3 * y3;
                    hb[qq*2]   = h2_bits(__floats2half2_rn(y0, y1));
                    hb[qq*2+1] = h2_bits(__floats2half2_rn(y2, y3));
                }
                float4 o0 = make_float4(__uint_as_float(hb[0]), __uint_as_float(hb[1]),
                                        __uint_as_float(hb[2]), __uint_as_float(hb[3]));
                float4 o1 = make_float4(__uint_as_float(hb[4]), __uint_as_float(hb[5]),
                                        __uint_as_float(hb[6]), __uint_as_float(hb[7]));
                __half* yr = g_Yh + (size_t)(eb + row) * DOUT + colbase;
                __stcs((float4*)yr, o0);
                __stcs((float4*)(yr + 8), o1);
            }
        }
        __syncthreads();
    }

    // ---- BN1 stats: reduce over g (lanes xor 4/8/16), then global atomics ----
    #pragma unroll
    for (int q = 0; q < 16; q++) {
        cs[q] += __shfl_xor_sync(0xffffffff, cs[q], 4);
        cs[q] += __shfl_xor_sync(0xffffffff, cs[q], 8);
        cs[q] += __shfl_xor_sync(0xffffffff, cs[q], 16);
        cq[q] += __shfl_xor_sync(0xffffffff, cq[q], 4);
        cq[q] += __shfl_xor_sync(0xffffffff, cq[q], 8);
        cq[q] += __shfl_xor_sync(0xffffffff, cq[q], 16);
    }
    if (g == 0) {
        #pragma unroll
        for (int q = 0; q < 16; q++) {
            atomicAdd(&g_colsum[colbase + q], cs[q]);
            atomicAdd(&g_colsq[colbase + q],  cq[q]);
        }
    }
}

__global__ void k_bn1fin(const float* __restrict__ gamma, const float* __restrict__ beta) {
    int j = threadIdx.x;
    float mean = g_colsum[j] * (1.0f / NEDGES);
    float var  = g_colsq[j] * (1.0f / NEDGES) - mean * mean;
    float aa = gamma[j] * rsqrtf(var + BN_EPS);
    g_a1[j] = aa;
    g_c1[j] = beta[j] - mean * aa;
}

// Pass 2: BN1 + gate + CSR segment sum + fused BN2 stats, software-pipelined.
__global__ void __launch_bounds__(256) k_msg() {
    __shared__ float sS[ELEM], sQ[ELEM];
    const int lane = threadIdx.x;
    const int tid  = threadIdx.y * 32 + lane;
    const int a = blockIdx.x * 8 + threadIdx.y;
    if (tid < ELEM) { sS[tid] = 0.f; sQ[tid] = 0.f; }
    __syncthreads();

    const int quarter = lane >> 3;
    const int j8 = lane & 7;

    float a1f[8], c1f[8], a1c[8], c1c[8];
    #pragma unroll
    for (int q = 0; q < 8; q++) {
        int j = 8 * j8 + q;
        a1f[q] = g_a1[j];      c1f[q] = g_c1[j];
        a1c[q] = g_a1[64 + j]; c1c[q] = g_c1[64 + j];
    }

    const int e0 = g_rowptr[a], e1 = g_rowptr[a + 1];
    float s[8];
    #pragma unroll
    for (int q = 0; q < 8; q++) s[q] = 0.f;
    const char* Yb = (const char*)g_Yh;

    int e = e0 + quarter;
    float4 fv, cv;
    if (e < e1) {
        fv = __ldcs((const float4*)(Yb + (size_t)e * 256 + j8 * 16));
        cv = __ldcs((const float4*)(Yb + (size_t)e * 256 + 128 + j8 * 16));
    }
    while (e < e1) {
        const int en = e + 4;
        float4 fvn, cvn;
        if (en < e1) {   // prefetch before the transcendental block
            fvn = __ldcs((const float4*)(Yb + (size_t)en * 256 + j8 * 16));
            cvn = __ldcs((const float4*)(Yb + (size_t)en * 256 + 128 + j8 * 16));
        }
        const __half2* f2 = (const __half2*)&fv;
        const __half2* c2 = (const __half2*)&cv;
        #pragma unroll
        for (int p = 0; p < 4; p++) {
            float yf0 = __low2float(f2[p])  * a1f[2*p]   + c1f[2*p];
            float yc0 = __low2float(c2[p])  * a1c[2*p]   + c1c[2*p];
            s[2*p]   += msg_gate(yf0, yc0);
            float yf1 = __high2float(f2[p]) * a1f[2*p+1] + c1f[2*p+1];
            float yc1 = __high2float(c2[p]) * a1c[2*p+1] + c1c[2*p+1];
            s[2*p+1] += msg_gate(yf1, yc1);
        }
        fv = fvn; cv = cvn; e = en;
    }
    #pragma unroll
    for (int q = 0; q < 8; q++) {
        s[q] += __shfl_xor_sync(0xffffffff, s[q], 8);
        s[q] += __shfl_xor_sync(0xffffffff, s[q], 16);
    }
    if (quarter == 0) {
        float4 st0 = make_float4(s[0], s[1], s[2], s[3]);
        float4 st1 = make_float4(s[4], s[5], s[6], s[7]);
        *(float4*)&g_sumed[(size_t)a * ELEM + j8 * 8]     = st0;
        *(float4*)&g_sumed[(size_t)a * ELEM + j8 * 8 + 4] = st1;
        #pragma unroll
        for (int q = 0; q < 8; q++) {
            atomicAdd(&sS[8 * j8 + q], s[q]);
            atomicAdd(&sQ[8 * j8 + q], s[q] * s[q]);
        }
    }
    __syncthreads();
    if (tid < ELEM) {
        atomicAdd(&g_s2[tid], sS[tid]);
        atomicAdd(&g_q2[tid], sQ[tid]);
    }
}

__global__ void k_bn2fin(const float* __restrict__ gamma, const float* __restrict__ beta) {
    int j = threadIdx.x;
    float mean = g_s2[j] * (1.0f / NATOMS);
    float var  = g_q2[j] * (1.0f / NATOMS) - mean * mean;
    float aa = gamma[j] * rsqrtf(var + BN_EPS);
    g_a2[j] = aa;
    g_c2[j] = beta[j] - mean * aa;
}

__global__ void k_final(const float* __restrict__ atom, float* __restrict__ out) {
    int i4 = blockIdx.x * blockDim.x + threadIdx.x;
    if (i4 >= NATOMS * ELEM / 4) return;
    int base = i4 * 4;
    int j = base & 63;
    float4 av = *(const float4*)(atom + base);
    float4 sv = *(const float4*)(g_sumed + base);
    float4 o;
    o.x = softplusf(av.x + sv.x * g_a2[j]     + g_c2[j]);
    o.y = softplusf(av.y + sv.y * g_a2[j + 1] + g_c2[j + 1]);
    o.z = softplusf(av.z + sv.z * g_a2[j + 2] + g_c2[j + 2]);
    o.w = softplusf(av.w + sv.w * g_a2[j + 3] + g_c2[j + 3]);
    *(float4*)(out + base) = o;
}

// ---------------- launch ----------------
extern "C" void kernel_launch(void* const* d_in, const int* in_sizes, int n_in,
                              void* d_out, int out_size) {
    const float* atom = (const float*)d_in[0];
    const float* nbr  = (const float*)d_in[1];
    const int*   sidx = (const int*)d_in[2];
    const int*   nidx = (const int*)d_in[3];
    const float* W    = (const float*)d_in[4];
    const float* bias = (const float*)d_in[5];
    const float* g1   = (const float*)d_in[6];
    const float* be1  = (const float*)d_in[7];
    const float* g2   = (const float*)d_in[8];
    const float* be2  = (const float*)d_in[9];
    float* out = (float*)d_out;

    cudaFuncSetAttribute(k_y_mma, cudaFuncAttributeMaxDynamicSharedMemorySize, SM_TOTAL);
    cudaFuncSetAttribute(k_precompute, cudaFuncAttributeMaxDynamicSharedMemorySize, PRE_SMEM);

    k_init<<<1, 128>>>();
    k_precompute<<<(NATOMS + 127) / 128, 256, PRE_SMEM>>>(atom, W, bias);
    k_rowptr<<<(NATOMS + 1 + 255) / 256, 256>>>(sidx);
    k_y_mma<<<GRID_Y, 256, SM_TOTAL>>>(nbr, sidx, nidx, W);
    k_bn1fin<<<1, DOUT>>>(g1, be1);
    dim3 mblk(32, 8);
    k_msg<<<NATOMS / 8, mblk>>>();
    k_bn2fin<<<1, ELEM>>>(g2, be2);
    k_final<<<(NATOMS * ELEM / 4 + 255) / 256, 256>>>(atom, out);
}

// round 9
// speedup vs baseline: 3.9050x; 1.0824x over previous
#include <cuda_runtime.h>
#include <cuda_bf16.h>
#include <cuda_fp16.h>
#include <math.h>
#include <stdint.h>

#define NATOMS 50000
#define NEDGES 800000
#define ELEM   64
#define DOUT   128
#define BN_EPS 1e-5f
#define NTILES (NEDGES / 128)     // 6250
#define GRID_Y 296                // persistent, 2 CTAs/SM

// ---------------- scratch (device globals; no allocation allowed) ----------------
__device__ __half g_P1h[(size_t)NATOMS * DOUT];  // atom @ W1 + b (fp16, 12.8MB)
__device__ __half g_P2h[(size_t)NATOMS * DOUT];  // atom @ W2     (fp16, 12.8MB)
__device__ __half g_Yh[(size_t)NEDGES * DOUT];   // pre-BN edge features, fp16
__device__ int    g_rowptr[NATOMS + 1];
__device__ float  g_colsum[DOUT];
__device__ float  g_colsq [DOUT];
__device__ float  g_a1[DOUT], g_c1[DOUT];
__device__ float  g_sumed[(size_t)NATOMS * ELEM];
__device__ float  g_s2[ELEM], g_q2[ELEM];
__device__ float  g_a2[ELEM], g_c2[ELEM];

// ---------------- helpers ----------------
__device__ __forceinline__ float softplusf(float x) {
    return log1pf(expf(-fabsf(x))) + fmaxf(x, 0.0f);
}
__device__ __forceinline__ float msg_gate(float yf, float yc) {
    float ef  = __expf(-yf);
    float sig = __fdividef(1.0f, 1.0f + ef);
    float ec  = __expf(-fabsf(yc));
    float sp  = __logf(1.0f + ec) + fmaxf(yc, 0.0f);
    return sig * sp;
}
__device__ __forceinline__ void fma4(float4& a, float x, const float4 w) {
    a.x += x * w.x; a.y += x * w.y; a.z += x * w.z; a.w += x * w.w;
}
__device__ __forceinline__ float4 add4(float4 a, float4 b) {
    return make_float4(a.x + b.x, a.y + b.y, a.z + b.z, a.w + b.w);
}
__device__ __forceinline__ void mma_bf16(float4& d, uint32_t a0, uint32_t a1,
                                         uint32_t a2, uint32_t a3,
                                         uint32_t b0, uint32_t b1) {
    asm volatile(
        "mma.sync.aligned.m16n8k16.row.col.f32.bf16.bf16.f32 "
        "{%0,%1,%2,%3}, {%4,%5,%6,%7}, {%8,%9}, {%0,%1,%2,%3};"
        : "+f"(d.x), "+f"(d.y), "+f"(d.z), "+f"(d.w)
        : "r"(a0), "r"(a1), "r"(a2), "r"(a3), "r"(b0), "r"(b1));
}
__device__ __forceinline__ uint32_t bf2_bits(__nv_bfloat162 h) {
    return *reinterpret_cast<uint32_t*>(&h);
}
__device__ __forceinline__ uint32_t h2_bits(__half2 h) {
    return *reinterpret_cast<uint32_t*>(&h);
}

// ---------------- SMEM layout for k_y (bytes) ----------------
#define LDA 72            // fp32 A leading dim
#define NPAD 20           // B packed: uint4 slots per n (16 used + 4 pad -> 320B stride)
#define SM_SIDX 0
#define SM_NIDX 512
#define SM_A    1024      // 128 x LDA fp32 = 36864
#define SM_BP   37888     // packed B: 128 x NPAD x 16B = 40960
#define SM_TOTAL 78848    // 77 KB -> 2 CTAs/SM

// ---------------- kernels ----------------
__global__ void k_init() {
    int t = threadIdx.x;
    if (t < DOUT) { g_colsum[t] = 0.f; g_colsq[t] = 0.f; }
    if (t < ELEM) { g_s2[t] = 0.f; g_q2[t] = 0.f; }
}

__global__ void k_rowptr(const int* __restrict__ sidx) {
    int a = blockIdx.x * blockDim.x + threadIdx.x;
    if (a > NATOMS) return;
    int lo = 0, hi = NEDGES;
    while (lo < hi) {
        int mid = (lo + hi) >> 1;
        if (sidx[mid] < a) lo = mid + 1; else hi = mid;
    }
    g_rowptr[a] = lo;
}

// P1 = atom @ W[0:64] + b ;  P2 = atom @ W[64:128].  128 atoms/block, fp16 out.
#define PRE_LDAT 68
#define PRE_SW   (64 * DOUT)
#define PRE_SMEM ((PRE_SW + 128 * PRE_LDAT) * 4)
__global__ void __launch_bounds__(256) k_precompute(const float* __restrict__ atom,
                                                    const float* __restrict__ W,
                                                    const float* __restrict__ bias) {
    extern __shared__ float psm[];
    float* sW  = psm;
    float* sAt = psm + PRE_SW;
    const int tid = threadIdx.x;
    const int ab = blockIdx.x * 128;
    const int nvalid = min(128, NATOMS - ab);

    #pragma unroll
    for (int p = 0; p < 8; p++) {
        int i4 = tid + p * 256;
        int a = i4 >> 4, kv = i4 & 15;
        float4 v = make_float4(0.f, 0.f, 0.f, 0.f);
        if (a < nvalid) v = *(const float4*)(atom + (size_t)(ab + a) * ELEM + kv * 4);
        *(float4*)&sAt[a * PRE_LDAT + kv * 4] = v;
    }

    const int a  = tid >> 1;
    const int ob = (tid & 1) * 64;

    for (int phase = 0; phase < 2; phase++) {
        __syncthreads();
        #pragma unroll
        for (int p = 0; p < 8; p++) {
            int i4 = tid + p * 256;
            int k = i4 >> 5, j4 = i4 & 31;
            *(float4*)&sW[k * DOUT + j4 * 4] =
                *(const float4*)(W + (size_t)(phase * 64 + k) * DOUT + j4 * 4);
        }
        __syncthreads();

        float4 acc[16];
        #pragma unroll
        for (int q = 0; q < 16; q++) acc[q] = make_float4(0.f, 0.f, 0.f, 0.f);
        #pragma unroll 4
        for (int k = 0; k < 64; k++) {
            float x = sAt[a * PRE_LDAT + k];
            #pragma unroll
            for (int q = 0; q < 16; q++) fma4(acc[q], x, *(float4*)&sW[k * DOUT + ob + q * 4]);
        }
        if (a < nvalid) {
            __half* dst = (phase == 0 ? g_P1h : g_P2h) + (size_t)(ab + a) * DOUT + ob;
            #pragma unroll
            for (int q = 0; q < 16; q += 2) {
                float4 vA = acc[q], vB = acc[q + 1];
                if (phase == 0) {
                    vA = add4(vA, *(const float4*)(bias + ob + q * 4));
                    vB = add4(vB, *(const float4*)(bias + ob + q * 4 + 4));
                }
                uint4 o;
                o.x = h2_bits(__floats2half2_rn(vA.x, vA.y));
                o.y = h2_bits(__floats2half2_rn(vA.z, vA.w));
                o.z = h2_bits(__floats2half2_rn(vB.x, vB.y));
                o.w = h2_bits(__floats2half2_rn(vB.z, vB.w));
                *(uint4*)(dst + q * 4) = o;
            }
        }
    }
}

// Pass 1 (raw HMMA, packed B, fp16 P tables): per 128-edge tile,
// G = nbr @ W3 via bf16 hi/lo split; epilogue from registers, 16 contiguous
// logical cols/thread (column-permuted B), 2x LDG.128 per P table per row.
__global__ void __launch_bounds__(256, 2) k_y_mma(const float* __restrict__ nbr,
                                                  const int* __restrict__ sidx,
                                                  const int* __restrict__ nidx,
                                                  const float* __restrict__ W) {
    extern __shared__ char sm[];
    int*   s_sidx = (int*)(sm + SM_SIDX);
    int*   s_nidx = (int*)(sm + SM_NIDX);
    float* sA     = (float*)(sm + SM_A);
    uint4* sBp    = (uint4*)(sm + SM_BP);

    const int tid  = threadIdx.x;
    const int wid  = tid >> 5;
    const int lane = tid & 31;
    const int wm   = wid >> 1;
    const int wn   = wid & 1;
    const int g    = lane >> 2;
    const int tg   = lane & 3;

    // Stage packed B: entry (n, ks, tgq) = uint4{bh(k0,k0+1), bh(k0+8,k0+9),
    // bl(k0,k0+1), bl(k0+8,k0+9)}, k0 = ks*16 + tgq*2, with column permutation
    // n -> logical W col h*64 + ((pp>>1)&3)*16 + (pp>>3)*2 + (pp&1).
    #pragma unroll
    for (int it = 0; it < 8; it++) {
        int idx = it * 256 + tid;          // 0..2047
        int n   = idx >> 4;
        int ks  = (idx >> 2) & 3;
        int tgq = idx & 3;
        int h = n >> 6, pp = n & 63;
        int l = ((pp >> 1) & 3) * 16 + (pp >> 3) * 2 + (pp & 1);
        int col = h * 64 + l;
        int k0 = ks * 16 + tgq * 2;
        float v0 = W[(size_t)(128 + k0)     * DOUT + col];
        float v1 = W[(size_t)(128 + k0 + 1) * DOUT + col];
        float v2 = W[(size_t)(128 + k0 + 8) * DOUT + col];
        float v3 = W[(size_t)(128 + k0 + 9) * DOUT + col];
        __nv_bfloat162 h01 = __float22bfloat162_rn(make_float2(v0, v1));
        __nv_bfloat162 h23 = __float22bfloat162_rn(make_float2(v2, v3));
        __nv_bfloat162 l01 = __float22bfloat162_rn(make_float2(
            v0 - __bfloat162float(__low2bfloat16(h01)), v1 - __bfloat162float(__high2bfloat16(h01))));
        __nv_bfloat162 l23 = __float22bfloat162_rn(make_float2(
            v2 - __bfloat162float(__low2bfloat16(h23)), v3 - __bfloat162float(__high2bfloat16(h23))));
        uint4 o;
        o.x = bf2_bits(h01); o.y = bf2_bits(h23);
        o.z = bf2_bits(l01); o.w = bf2_bits(l23);
        sBp[(size_t)n * NPAD + ks * 4 + tgq] = o;
    }
    __syncthreads();

    // persistent BN1 stats: 16 logical columns owned by this thread
    float cs[16], cq[16];
    #pragma unroll
    for (int q = 0; q < 16; q++) { cs[q] = 0.f; cq[q] = 0.f; }
    const int colbase = wn * 64 + tg * 16;

    for (int t = blockIdx.x; t < NTILES; t += GRID_Y) {
        const int eb = t * 128;

        // ---- stage A tile fp32 (streaming reads) ----
        float4 v[8];
        #pragma unroll
        for (int p = 0; p < 8; p++)
            v[p] = __ldcs((const float4*)(nbr + (size_t)eb * ELEM) + tid + p * 256);
        if (tid < 128) {
            s_sidx[tid] = __ldg(sidx + eb + tid);
            s_nidx[tid] = __ldg(nidx + eb + tid);
        }
        #pragma unroll
        for (int p = 0; p < 8; p++) {
            int i4 = tid + p * 256;
            int row = i4 >> 4, kv = i4 & 15;
            *(float4*)&sA[row * LDA + kv * 4] = v[p];
        }
        __syncthreads();

        // ---- MMA: acc = Ah*Bh + Ah*Bl + Al*Bh ----
        float4 acc[2][8];
        #pragma unroll
        for (int i = 0; i < 2; i++)
            #pragma unroll
            for (int j = 0; j < 8; j++)
                acc[i][j] = make_float4(0.f, 0.f, 0.f, 0.f);

        #pragma unroll
        for (int ks = 0; ks < 4; ks++) {
            const int c0 = ks * 16 + tg * 2;
            uint32_t ah[2][4], al[2][4];
            #pragma unroll
            for (int i = 0; i < 2; i++) {
                const float* rlo = sA + (wm * 32 + i * 16 + g) * LDA;
                const float* rhi = rlo + 8 * LDA;
                float2 w0 = *(const float2*)(rlo + c0);
                float2 w1 = *(const float2*)(rhi + c0);
                float2 w2 = *(const float2*)(rlo + c0 + 8);
                float2 w3 = *(const float2*)(rhi + c0 + 8);
                __nv_bfloat162 h0 = __float22bfloat162_rn(w0);
                __nv_bfloat162 h1 = __float22bfloat162_rn(w1);
                __nv_bfloat162 h2 = __float22bfloat162_rn(w2);
                __nv_bfloat162 h3 = __float22bfloat162_rn(w3);
                ah[i][0] = bf2_bits(h0); ah[i][1] = bf2_bits(h1);
                ah[i][2] = bf2_bits(h2); ah[i][3] = bf2_bits(h3);
                al[i][0] = bf2_bits(__float22bfloat162_rn(make_float2(
                    w0.x - __bfloat162float(__low2bfloat16(h0)), w0.y - __bfloat162float(__high2bfloat16(h0)))));
                al[i][1] = bf2_bits(__float22bfloat162_rn(make_float2(
                    w1.x - __bfloat162float(__low2bfloat16(h1)), w1.y - __bfloat162float(__high2bfloat16(h1)))));
                al[i][2] = bf2_bits(__float22bfloat162_rn(make_float2(
                    w2.x - __bfloat162float(__low2bfloat16(h2)), w2.y - __bfloat162float(__high2bfloat16(h2)))));
                al[i][3] = bf2_bits(__float22bfloat162_rn(make_float2(
                    w3.x - __bfloat162float(__low2bfloat16(h3)), w3.y - __bfloat162float(__high2bfloat16(h3)))));
            }
            #pragma unroll
            for (int j = 0; j < 8; j++) {
                const int n = wn * 64 + j * 8 + g;
                uint4 bb = sBp[(size_t)n * NPAD + ks * 4 + tg];
                #pragma unroll
                for (int i = 0; i < 2; i++) {
                    mma_bf16(acc[i][j], ah[i][0], ah[i][1], ah[i][2], ah[i][3], bb.x, bb.y);
                    mma_bf16(acc[i][j], ah[i][0], ah[i][1], ah[i][2], ah[i][3], bb.z, bb.w);
                    mma_bf16(acc[i][j], al[i][0], al[i][1], al[i][2], al[i][3], bb.x, bb.y);
                }
            }
        }

        // ---- epilogue: 16 contiguous cols/thread; fp16 P tables (2x uint4 each) ----
        #pragma unroll
        for (int i = 0; i < 2; i++) {
            #pragma unroll
            for (int rr = 0; rr < 2; rr++) {
                const int row = wm * 32 + i * 16 + rr * 8 + g;
                const int s = s_sidx[row], n = s_nidx[row];
                uint4 p1u[2], p2u[2];
                p1u[0] = __ldg((const uint4*)(g_P1h + (size_t)s * DOUT + colbase));
                p1u[1] = __ldg((const uint4*)(g_P1h + (size_t)s * DOUT + colbase + 8));
                p2u[0] = __ldg((const uint4*)(g_P2h + (size_t)n * DOUT + colbase));
                p2u[1] = __ldg((const uint4*)(g_P2h + (size_t)n * DOUT + colbase + 8));
                const __half2* ph1 = (const __half2*)p1u;   // 8 half2 = 16 halves
                const __half2* ph2 = (const __half2*)p2u;
                uint32_t hb[8];
                #pragma unroll
                for (int j = 0; j < 8; j++) {
                    float2 p1 = __half22float2(ph1[j]);
                    float2 p2 = __half22float2(ph2[j]);
                    float y0 = (rr ? acc[i][j].z : acc[i][j].x) + p1.x + p2.x;
                    float y1 = (rr ? acc[i][j].w : acc[i][j].y) + p1.y + p2.y;
                    cs[2 * j]     += y0; cq[2 * j]     += y0 * y0;
                    cs[2 * j + 1] += y1; cq[2 * j + 1] += y1 * y1;
                    hb[j] = h2_bits(__floats2half2_rn(y0, y1));
                }
                float4 o0 = make_float4(__uint_as_float(hb[0]), __uint_as_float(hb[1]),
                                        __uint_as_float(hb[2]), __uint_as_float(hb[3]));
                float4 o1 = make_float4(__uint_as_float(hb[4]), __uint_as_float(hb[5]),
                                        __uint_as_float(hb[6]), __uint_as_float(hb[7]));
                __half* yr = g_Yh + (size_t)(eb + row) * DOUT + colbase;
                __stcs((float4*)yr, o0);
                __stcs((float4*)(yr + 8), o1);
            }
        }
        __syncthreads();
    }

    // ---- BN1 stats reduce + global atomics ----
    #pragma unroll
    for (int q = 0; q < 16; q++) {
        cs[q] += __shfl_xor_sync(0xffffffff, cs[q], 4);
        cs[q] += __shfl_xor_sync(0xffffffff, cs[q], 8);
        cs[q] += __shfl_xor_sync(0xffffffff, cs[q], 16);
        cq[q] += __shfl_xor_sync(0xffffffff, cq[q], 4);
        cq[q] += __shfl_xor_sync(0xffffffff, cq[q], 8);
        cq[q] += __shfl_xor_sync(0xffffffff, cq[q], 16);
    }
    if (g == 0) {
        #pragma unroll
        for (int q = 0; q < 16; q++) {
            atomicAdd(&g_colsum[colbase + q], cs[q]);
            atomicAdd(&g_colsq[colbase + q],  cq[q]);
        }
    }
}

__global__ void k_bn1fin(const float* __restrict__ gamma, const float* __restrict__ beta) {
    int j = threadIdx.x;
    float mean = g_colsum[j] * (1.0f / NEDGES);
    float var  = g_colsq[j] * (1.0f / NEDGES) - mean * mean;
    float aa = gamma[j] * rsqrtf(var + BN_EPS);
    g_a1[j] = aa;
    g_c1[j] = beta[j] - mean * aa;
}

// Pass 2: BN1 + gate + CSR segment sum + fused BN2 stats, software-pipelined.
__global__ void __launch_bounds__(256) k_msg() {
    __shared__ float sS[ELEM], sQ[ELEM];
    const int lane = threadIdx.x;
    const int tid  = threadIdx.y * 32 + lane;
    const int a = blockIdx.x * 8 + threadIdx.y;
    if (tid < ELEM) { sS[tid] = 0.f; sQ[tid] = 0.f; }
    __syncthreads();

    const int quarter = lane >> 3;
    const int j8 = lane & 7;

    float a1f[8], c1f[8], a1c[8], c1c[8];
    #pragma unroll
    for (int q = 0; q < 8; q++) {
        int j = 8 * j8 + q;
        a1f[q] = g_a1[j];      c1f[q] = g_c1[j];
        a1c[q] = g_a1[64 + j]; c1c[q] = g_c1[64 + j];
    }

    const int e0 = g_rowptr[a], e1 = g_rowptr[a + 1];
    float s[8];
    #pragma unroll
    for (int q = 0; q < 8; q++) s[q] = 0.f;
    const char* Yb = (const char*)g_Yh;

    int e = e0 + quarter;
    float4 fv, cv;
    if (e < e1) {
        fv = __ldcs((const float4*)(Yb + (size_t)e * 256 + j8 * 16));
        cv = __ldcs((const float4*)(Yb + (size_t)e * 256 + 128 + j8 * 16));
    }
    while (e < e1) {
        const int en = e + 4;
        float4 fvn, cvn;
        if (en < e1) {
            fvn = __ldcs((const float4*)(Yb + (size_t)en * 256 + j8 * 16));
            cvn = __ldcs((const float4*)(Yb + (size_t)en * 256 + 128 + j8 * 16));
        }
        const __half2* f2 = (const __half2*)&fv;
        const __half2* c2 = (const __half2*)&cv;
        #pragma unroll
        for (int p = 0; p < 4; p++) {
            float yf0 = __low2float(f2[p])  * a1f[2*p]   + c1f[2*p];
            float yc0 = __low2float(c2[p])  * a1c[2*p]   + c1c[2*p];
            s[2*p]   += msg_gate(yf0, yc0);
            float yf1 = __high2float(f2[p]) * a1f[2*p+1] + c1f[2*p+1];
            float yc1 = __high2float(c2[p]) * a1c[2*p+1] + c1c[2*p+1];
            s[2*p+1] += msg_gate(yf1, yc1);
        }
        fv = fvn; cv = cvn; e = en;
    }
    #pragma unroll
    for (int q = 0; q < 8; q++) {
        s[q] += __shfl_xor_sync(0xffffffff, s[q], 8);
        s[q] += __shfl_xor_sync(0xffffffff, s[q], 16);
    }
    if (quarter == 0) {
        float4 st0 = make_float4(s[0], s[1], s[2], s[3]);
        float4 st1 = make_float4(s[4], s[5], s[6], s[7]);
        *(float4*)&g_sumed[(size_t)a * ELEM + j8 * 8]     = st0;
        *(float4*)&g_sumed[(size_t)a * ELEM + j8 * 8 + 4] = st1;
        #pragma unroll
        for (int q = 0; q < 8; q++) {
            atomicAdd(&sS[8 * j8 + q], s[q]);
            atomicAdd(&sQ[8 * j8 + q], s[q] * s[q]);
        }
    }
    __syncthreads();
    if (tid < ELEM) {
        atomicAdd(&g_s2[tid], sS[tid]);
        atomicAdd(&g_q2[tid], sQ[tid]);
    }
}

__global__ void k_bn2fin(const float* __restrict__ gamma, const float* __restrict__ beta) {
    int j = threadIdx.x;
    float mean = g_s2[j] * (1.0f / NATOMS);
    float var  = g_q2[j] * (1.0f / NATOMS) - mean * mean;
    float aa = gamma[j] * rsqrtf(var + BN_EPS);
    g_a2[j] = aa;
    g_c2[j] = beta[j] - mean * aa;
}

__global__ void k_final(const float* __restrict__ atom, float* __restrict__ out) {
    int i4 = blockIdx.x * blockDim.x + threadIdx.x;
    if (i4 >= NATOMS * ELEM / 4) return;
    int base = i4 * 4;
    int j = base & 63;
    float4 av = *(const float4*)(atom + base);
    float4 sv = *(const float4*)(g_sumed + base);
    float4 o;
    o.x = softplusf(av.x + sv.x * g_a2[j]     + g_c2[j]);
    o.y = softplusf(av.y + sv.y * g_a2[j + 1] + g_c2[j + 1]);
    o.z = softplusf(av.z + sv.z * g_a2[j + 2] + g_c2[j + 2]);
    o.w = softplusf(av.w + sv.w * g_a2[j + 3] + g_c2[j + 3]);
    *(float4*)(out + base) = o;
}

// ---------------- launch ----------------
extern "C" void kernel_launch(void* const* d_in, const int* in_sizes, int n_in,
                              void* d_out, int out_size) {
    const float* atom = (const float*)d_in[0];
    const float* nbr  = (const float*)d_in[1];
    const int*   sidx = (const int*)d_in[2];
    const int*   nidx = (const int*)d_in[3];
    const float* W    = (const float*)d_in[4];
    const float* bias = (const float*)d_in[5];
    const float* g1   = (const float*)d_in[6];
    const float* be1  = (const float*)d_in[7];
    const float* g2   = (const float*)d_in[8];
    const float* be2  = (const float*)d_in[9];
    float* out = (float*)d_out;

    cudaFuncSetAttribute(k_y_mma, cudaFuncAttributeMaxDynamicSharedMemorySize, SM_TOTAL);
    cudaFuncSetAttribute(k_precompute, cudaFuncAttributeMaxDynamicSharedMemorySize, PRE_SMEM);

    k_init<<<1, 128>>>();
    k_precompute<<<(NATOMS + 127) / 128, 256, PRE_SMEM>>>(atom, W, bias);
    k_rowptr<<<(NATOMS + 1 + 255) / 256, 256>>>(sidx);
    k_y_mma<<<GRID_Y, 256, SM_TOTAL>>>(nbr, sidx, nidx, W);
    k_bn1fin<<<1, DOUT>>>(g1, be1);
    dim3 mblk(32, 8);
    k_msg<<<NATOMS / 8, mblk>>>();
    k_bn2fin<<<1, ELEM>>>(g2, be2);
    k_final<<<(NATOMS * ELEM / 4 + 255) / 256, 256>>>(atom, out);
}